// round 1
// baseline (speedup 1.0000x reference)
#include <cuda_runtime.h>

#define BB 32
#define SS 256
#define HH 768
#define NH 12
#define HD 64
#define BH (BB*NH)          // 384

// Scratch (device globals; no runtime allocation)
__device__ float g_q[BH*SS*HD];
__device__ float g_k[BH*SS*HD];
__device__ float g_v[BH*SS*HD];
__device__ float g_p[(size_t)BH*SS*SS];

// ---------------------------------------------------------------------------
// Kernel 1: QKV projection.  Y = X @ W + b, X:[8192,768], W:[768,768].
// Output written in [B, NH, S, HD] layout. blockIdx.z selects Q/K/V.
// Tiles: BM=128, BN=128, BK=8, 256 threads, 8x8 microtile.
// ---------------------------------------------------------------------------
__global__ __launch_bounds__(256) void qkv_kernel(
    const float* __restrict__ X,
    const float* __restrict__ Wq, const float* __restrict__ bq,
    const float* __restrict__ Wk, const float* __restrict__ bk,
    const float* __restrict__ Wv, const float* __restrict__ bv)
{
    const int z = blockIdx.z;
    const float* W    = (z == 0) ? Wq : (z == 1) ? Wk : Wv;
    const float* bias = (z == 0) ? bq : (z == 1) ? bk : bv;
    float* dst        = (z == 0) ? g_q : (z == 1) ? g_k : g_v;

    __shared__ float As[8][128];   // A transposed: As[k][m]
    __shared__ float Bs[8][128];   // Bs[k][n]

    const int m0 = blockIdx.y * 128;
    const int n0 = blockIdx.x * 128;
    const int tid = threadIdx.x;
    const int ty = tid >> 4, tx = tid & 15;

    const int arow = tid >> 1;             // 0..127
    const int ac4  = (tid & 1) * 4;        // 0 or 4
    const int brow = tid >> 5;             // 0..7
    const int bcol = (tid & 31) * 4;       // 0..124

    float acc[8][8];
    #pragma unroll
    for (int i = 0; i < 8; i++)
        #pragma unroll
        for (int j = 0; j < 8; j++) acc[i][j] = 0.f;

    for (int k0 = 0; k0 < HH; k0 += 8) {
        float4 av = *(const float4*)&X[(size_t)(m0 + arow) * HH + k0 + ac4];
        As[ac4 + 0][arow] = av.x;
        As[ac4 + 1][arow] = av.y;
        As[ac4 + 2][arow] = av.z;
        As[ac4 + 3][arow] = av.w;
        float4 bv4 = *(const float4*)&W[(size_t)(k0 + brow) * HH + n0 + bcol];
        *(float4*)&Bs[brow][bcol] = bv4;
        __syncthreads();

        #pragma unroll
        for (int k = 0; k < 8; k++) {
            float a[8], b[8];
            *(float4*)(a)     = *(const float4*)&As[k][ty * 8];
            *(float4*)(a + 4) = *(const float4*)&As[k][ty * 8 + 4];
            *(float4*)(b)     = *(const float4*)&Bs[k][tx * 8];
            *(float4*)(b + 4) = *(const float4*)&Bs[k][tx * 8 + 4];
            #pragma unroll
            for (int i = 0; i < 8; i++)
                #pragma unroll
                for (int j = 0; j < 8; j++)
                    acc[i][j] += a[i] * b[j];
        }
        __syncthreads();
    }

    // Epilogue: bias + scatter into [B, NH, S, HD]
    #pragma unroll
    for (int i = 0; i < 8; i++) {
        const int m  = m0 + ty * 8 + i;
        const int b_ = m >> 8;        // / 256
        const int s  = m & 255;
        #pragma unroll
        for (int j = 0; j < 8; j++) {
            const int n = n0 + tx * 8 + j;
            const int h = n >> 6;
            const int d = n & 63;
            dst[(size_t)((b_ * NH + h) * SS + s) * HD + d] = acc[i][j] + bias[n];
        }
    }
}

// ---------------------------------------------------------------------------
// Kernel 2: scores = softmax( (Q K^T / 8) * (w*CM + bc) + mask ), write probs.
// One block per (b,h, 64-row q-tile). K fully staged (transposed) in smem so
// each warp owns 8 full 256-wide rows -> fused softmax, no second pass.
// Dynamic smem: Qs[64][64] + KT[64][256] = 80 KB.
// ---------------------------------------------------------------------------
__global__ __launch_bounds__(256) void scores_kernel(
    const float* __restrict__ CM,     // [B,1,S,S]
    const float* __restrict__ MSK,    // [B,1,1,S]
    const float* __restrict__ wcm_p,  // scalar
    const float* __restrict__ bcm_p)  // scalar
{
    extern __shared__ float sm[];
    float* Qs = sm;            // [d*64 + m]
    float* KT = sm + 64 * 64;  // [d*256 + j]

    const int bh = blockIdx.y;
    const int qt = blockIdx.x;          // 0..3
    const int b  = bh / NH;
    const int tid = threadIdx.x;

    const float* Q = g_q + (size_t)bh * SS * HD;
    const float* K = g_k + (size_t)bh * SS * HD;

    // Stage Q tile (64 rows), transposed
    for (int idx = tid; idx < 64 * 16; idx += 256) {
        const int row = idx >> 4;
        const int c4  = (idx & 15) * 4;
        float4 v = *(const float4*)&Q[(size_t)(qt * 64 + row) * HD + c4];
        Qs[(c4 + 0) * 64 + row] = v.x;
        Qs[(c4 + 1) * 64 + row] = v.y;
        Qs[(c4 + 2) * 64 + row] = v.z;
        Qs[(c4 + 3) * 64 + row] = v.w;
    }
    // Stage all of K (256 rows), transposed
    for (int idx = tid; idx < 256 * 16; idx += 256) {
        const int j  = idx >> 4;
        const int c4 = (idx & 15) * 4;
        float4 v = *(const float4*)&K[(size_t)j * HD + c4];
        KT[(c4 + 0) * 256 + j] = v.x;
        KT[(c4 + 1) * 256 + j] = v.y;
        KT[(c4 + 2) * 256 + j] = v.z;
        KT[(c4 + 3) * 256 + j] = v.w;
    }
    __syncthreads();

    const int trow = tid >> 5;   // warp id: rows trow*8 .. trow*8+7
    const int lane = tid & 31;   // cols lane + 32*t

    float acc[8][8];
    #pragma unroll
    for (int i = 0; i < 8; i++)
        #pragma unroll
        for (int t = 0; t < 8; t++) acc[i][t] = 0.f;

    #pragma unroll 4
    for (int d = 0; d < 64; d++) {
        float a[8], bb[8];
        *(float4*)(a)     = *(const float4*)&Qs[d * 64 + trow * 8];
        *(float4*)(a + 4) = *(const float4*)&Qs[d * 64 + trow * 8 + 4];
        #pragma unroll
        for (int t = 0; t < 8; t++) bb[t] = KT[d * 256 + lane + 32 * t];
        #pragma unroll
        for (int i = 0; i < 8; i++)
            #pragma unroll
            for (int t = 0; t < 8; t++)
                acc[i][t] += a[i] * bb[t];
    }

    const float wcm = wcm_p[0];
    const float bcm = bcm_p[0];

    #pragma unroll
    for (int i = 0; i < 8; i++) {
        const int r = qt * 64 + trow * 8 + i;   // global q row
        float s[8];
        float mx = -1e30f;
        #pragma unroll
        for (int t = 0; t < 8; t++) {
            const int c = lane + 32 * t;
            const float cmv = wcm * CM[(size_t)b * SS * SS + (size_t)r * SS + c] + bcm;
            s[t] = acc[i][t] * 0.125f * cmv + MSK[b * SS + c];
            mx = fmaxf(mx, s[t]);
        }
        #pragma unroll
        for (int o = 16; o; o >>= 1) mx = fmaxf(mx, __shfl_xor_sync(0xffffffffu, mx, o));
        float sum = 0.f;
        #pragma unroll
        for (int t = 0; t < 8; t++) { s[t] = __expf(s[t] - mx); sum += s[t]; }
        #pragma unroll
        for (int o = 16; o; o >>= 1) sum += __shfl_xor_sync(0xffffffffu, sum, o);
        const float inv = 1.f / sum;
        float* prow = g_p + ((size_t)bh * SS + r) * SS;
        #pragma unroll
        for (int t = 0; t < 8; t++) prow[lane + 32 * t] = s[t] * inv;
    }
}

// ---------------------------------------------------------------------------
// Kernel 3: ctx = P @ V, per (b,h): [256,256]@[256,64] -> out [B,S,H] layout.
// Tiles: BM=128, BN=64, BK=32, 256 threads, 8x4 microtile.
// ---------------------------------------------------------------------------
__global__ __launch_bounds__(256) void pv_kernel(float* __restrict__ out)
{
    __shared__ float PsT[32][128];   // P transposed: PsT[k][m]
    __shared__ float Vs[32][64];     // Vs[k][n]

    const int bh = blockIdx.y;
    const int mt = blockIdx.x;        // 0..1
    const int b  = bh / NH;
    const int h  = bh % NH;
    const int m0 = mt * 128;
    const int tid = threadIdx.x;
    const int ty = tid >> 4, tx = tid & 15;

    const float* P = g_p + (size_t)bh * SS * SS;
    const float* V = g_v + (size_t)bh * SS * HD;

    float acc[8][4];
    #pragma unroll
    for (int i = 0; i < 8; i++)
        #pragma unroll
        for (int j = 0; j < 4; j++) acc[i][j] = 0.f;

    for (int k0 = 0; k0 < SS; k0 += 32) {
        #pragma unroll
        for (int u = 0; u < 4; u++) {
            const int idx = tid + u * 256;      // 0..1023
            const int row = idx >> 3;           // 0..127
            const int c4  = (idx & 7) * 4;      // 0..28
            float4 v = *(const float4*)&P[(size_t)(m0 + row) * SS + k0 + c4];
            PsT[c4 + 0][row] = v.x;
            PsT[c4 + 1][row] = v.y;
            PsT[c4 + 2][row] = v.z;
            PsT[c4 + 3][row] = v.w;
        }
        #pragma unroll
        for (int u = 0; u < 2; u++) {
            const int idx = tid + u * 256;      // 0..511
            const int row = idx >> 4;           // 0..31
            const int c4  = (idx & 15) * 4;     // 0..60
            *(float4*)&Vs[row][c4] = *(const float4*)&V[(size_t)(k0 + row) * HD + c4];
        }
        __syncthreads();

        #pragma unroll
        for (int k = 0; k < 32; k++) {
            float a[8], bb[4];
            *(float4*)(a)     = *(const float4*)&PsT[k][ty * 8];
            *(float4*)(a + 4) = *(const float4*)&PsT[k][ty * 8 + 4];
            *(float4*)(bb)    = *(const float4*)&Vs[k][tx * 4];
            #pragma unroll
            for (int i = 0; i < 8; i++)
                #pragma unroll
                for (int j = 0; j < 4; j++)
                    acc[i][j] += a[i] * bb[j];
        }
        __syncthreads();
    }

    #pragma unroll
    for (int i = 0; i < 8; i++) {
        const int s = m0 + ty * 8 + i;
        float* orow = out + (size_t)(b * SS + s) * HH + h * HD + tx * 4;
        #pragma unroll
        for (int j = 0; j < 4; j++) orow[j] = acc[i][j];
    }
}

// ---------------------------------------------------------------------------
extern "C" void kernel_launch(void* const* d_in, const int* in_sizes, int n_in,
                              void* d_out, int out_size)
{
    const float* X    = (const float*)d_in[0];   // hidden_states [B,S,H]
    const float* CM   = (const float*)d_in[1];   // contact_map   [B,1,S,S]
    const float* MSK  = (const float*)d_in[2];   // attention_mask[B,1,1,S]
    const float* Wq   = (const float*)d_in[3];
    const float* bq   = (const float*)d_in[4];
    const float* Wk   = (const float*)d_in[5];
    const float* bk   = (const float*)d_in[6];
    const float* Wv   = (const float*)d_in[7];
    const float* bv   = (const float*)d_in[8];
    const float* wcm  = (const float*)d_in[9];
    const float* bcm  = (const float*)d_in[10];
    float* out = (float*)d_out;

    // 1) QKV projections: grid (N/128, M/128, 3)
    qkv_kernel<<<dim3(HH / 128, (BB * SS) / 128, 3), 256>>>(X, Wq, bq, Wk, bk, Wv, bv);

    // 2) scores + softmax (80 KB dynamic smem)
    const size_t smem2 = (64 * 64 + 64 * 256) * sizeof(float);
    cudaFuncSetAttribute(scores_kernel, cudaFuncAttributeMaxDynamicSharedMemorySize, (int)smem2);
    scores_kernel<<<dim3(4, BH), 256, smem2>>>(CM, MSK, wcm, bcm);

    // 3) P @ V
    pv_kernel<<<dim3(2, BH), 256>>>(out);
}

// round 3
// speedup vs baseline: 1.8261x; 1.8261x over previous
#include <cuda_runtime.h>
#include <cuda_bf16.h>
#include <cstdint>

#define BB 32
#define SS 256
#define HH 768
#define NH 12
#define HD 64
#define BH (BB*NH)          // 384

// Scratch (device globals; no runtime allocation)
__device__ float g_q[BH*SS*HD];
__device__ float g_k[BH*SS*HD];
__device__ float g_v[BH*SS*HD];
__device__ float g_p[(size_t)BH*SS*SS];

// bf16 hi/lo split operands for the QKV GEMM
__device__ unsigned short g_xh[(size_t)BB*SS*HH];
__device__ unsigned short g_xl[(size_t)BB*SS*HH];
__device__ unsigned short g_wh[(size_t)3*HH*HH];   // transposed: [nw][n][k]
__device__ unsigned short g_wl[(size_t)3*HH*HH];

// ---------------------------------------------------------------------------
// mma.sync helpers (sm_80-era PTX; legal on plain sm_100 target)
// ---------------------------------------------------------------------------
__device__ __forceinline__ uint32_t smem_to_u32(const void* p) {
    uint32_t a;
    asm("{ .reg .u64 t; cvta.to.shared.u64 t, %1; cvt.u32.u64 %0, t; }" : "=r"(a) : "l"(p));
    return a;
}
__device__ __forceinline__ void ldm_x4(uint32_t* r, uint32_t addr) {
    asm volatile("ldmatrix.sync.aligned.m8n8.x4.shared.b16 {%0,%1,%2,%3}, [%4];"
        : "=r"(r[0]), "=r"(r[1]), "=r"(r[2]), "=r"(r[3]) : "r"(addr));
}
__device__ __forceinline__ void mma16816(float* c, const uint32_t* a, const uint32_t* b) {
    asm volatile("mma.sync.aligned.m16n8k16.row.col.f32.bf16.bf16.f32 "
        "{%0,%1,%2,%3}, {%4,%5,%6,%7}, {%8,%9}, {%0,%1,%2,%3};"
        : "+f"(c[0]), "+f"(c[1]), "+f"(c[2]), "+f"(c[3])
        : "r"(a[0]), "r"(a[1]), "r"(a[2]), "r"(a[3]), "r"(b[0]), "r"(b[1]));
}

// ---------------------------------------------------------------------------
// Prep kernels: fp32 -> bf16 hi/lo split
// ---------------------------------------------------------------------------
__global__ __launch_bounds__(256) void prep_x(const float* __restrict__ X)
{
    const size_t i4 = (size_t)blockIdx.x * 256 + threadIdx.x;   // float4 index
    if (i4 * 4 >= (size_t)BB * SS * HH) return;
    float4 v = ((const float4*)X)[i4];
    __nv_bfloat16 h0 = __float2bfloat16(v.x), h1 = __float2bfloat16(v.y);
    __nv_bfloat16 h2 = __float2bfloat16(v.z), h3 = __float2bfloat16(v.w);
    __nv_bfloat16 l0 = __float2bfloat16(v.x - __bfloat162float(h0));
    __nv_bfloat16 l1 = __float2bfloat16(v.y - __bfloat162float(h1));
    __nv_bfloat16 l2 = __float2bfloat16(v.z - __bfloat162float(h2));
    __nv_bfloat16 l3 = __float2bfloat16(v.w - __bfloat162float(h3));
    ((ushort4*)g_xh)[i4] = make_ushort4(__bfloat16_as_ushort(h0), __bfloat16_as_ushort(h1),
                                        __bfloat16_as_ushort(h2), __bfloat16_as_ushort(h3));
    ((ushort4*)g_xl)[i4] = make_ushort4(__bfloat16_as_ushort(l0), __bfloat16_as_ushort(l1),
                                        __bfloat16_as_ushort(l2), __bfloat16_as_ushort(l3));
}

__global__ __launch_bounds__(256) void prep_w(
    const float* __restrict__ Wq, const float* __restrict__ Wk, const float* __restrict__ Wv)
{
    const size_t idx = (size_t)blockIdx.x * 256 + threadIdx.x;   // [nw][n][k]
    if (idx >= (size_t)3 * HH * HH) return;
    const int k  = idx % HH;
    const int n  = (idx / HH) % HH;
    const int nw = idx / (HH * HH);
    const float* W = (nw == 0) ? Wq : (nw == 1) ? Wk : Wv;
    float v = __ldg(&W[(size_t)k * HH + n]);
    __nv_bfloat16 h = __float2bfloat16(v);
    __nv_bfloat16 l = __float2bfloat16(v - __bfloat162float(h));
    g_wh[idx] = __bfloat16_as_ushort(h);
    g_wl[idx] = __bfloat16_as_ushort(l);
}

// ---------------------------------------------------------------------------
// QKV GEMM via mma.sync bf16 (3-term split, fp32 accumulators).
// CTA tile 128(M) x 128(N), K chunk 32; 8 warps in 2x4; warp tile 64x32.
// grid = (64 m-blocks, 3 weights * 6 n-blocks), 256 threads.
// ---------------------------------------------------------------------------
#define PITCH 40     // bf16 elements per smem row (80B) -> conflict-free ldmatrix

__global__ __launch_bounds__(256, 2) void qkv_mma(
    const float* __restrict__ bq, const float* __restrict__ bk, const float* __restrict__ bv)
{
    __shared__ __align__(16) unsigned short sAh[128 * PITCH];
    __shared__ __align__(16) unsigned short sAl[128 * PITCH];
    __shared__ __align__(16) unsigned short sBh[128 * PITCH];
    __shared__ __align__(16) unsigned short sBl[128 * PITCH];

    const int tid  = threadIdx.x;
    const int wid  = tid >> 5;
    const int lane = tid & 31;

    const int m0 = blockIdx.x * 128;
    const int nw = blockIdx.y / 6;
    const int n0 = (blockIdx.y % 6) * 128;

    const float* bias = (nw == 0) ? bq : (nw == 1) ? bk : bv;
    float* dst        = (nw == 0) ? g_q : (nw == 1) ? g_k : g_v;

    const int wm = (wid >> 2) * 64;     // warp m base within CTA tile
    const int wn = (wid & 3) * 32;      // warp n base

    const uint32_t sAh_b = smem_to_u32(sAh);
    const uint32_t sAl_b = smem_to_u32(sAl);
    const uint32_t sBh_b = smem_to_u32(sBh);
    const uint32_t sBl_b = smem_to_u32(sBl);

    // ldmatrix per-lane offsets (bytes), before m/n-tile and k-step adds
    const uint32_t a_off = ((wm + (lane & 15)) * PITCH + (lane >> 4) * 8) * 2;
    const uint32_t b_off = ((wn + (lane >> 4) * 8 + (lane & 7)) * PITCH + ((lane >> 3) & 1) * 8) * 2;

    float acc[4][4][4];
    #pragma unroll
    for (int i = 0; i < 4; i++)
        #pragma unroll
        for (int j = 0; j < 4; j++)
            #pragma unroll
            for (int c = 0; c < 4; c++) acc[i][j][c] = 0.f;

    for (int chunk = 0; chunk < 24; chunk++) {
        const int k0 = chunk * 32;
        // Stage A (Xh, Xl) and B (Wh, Wl): 128 rows x 32 bf16 each
        #pragma unroll
        for (int i = 0; i < 2; i++) {
            const int idx = tid + i * 256;       // 0..511
            const int r  = idx >> 2;
            const int sg = idx & 3;
            const size_t ga = (size_t)(m0 + r) * HH + k0 + sg * 8;
            const size_t gb = ((size_t)nw * HH + n0 + r) * HH + k0 + sg * 8;
            const uint32_t so = r * PITCH + sg * 8;
            *(uint4*)&sAh[so] = *(const uint4*)&g_xh[ga];
            *(uint4*)&sAl[so] = *(const uint4*)&g_xl[ga];
            *(uint4*)&sBh[so] = *(const uint4*)&g_wh[gb];
            *(uint4*)&sBl[so] = *(const uint4*)&g_wl[gb];
        }
        __syncthreads();

        #pragma unroll
        for (int ks = 0; ks < 2; ks++) {
            const uint32_t kadd = ks * 16 * 2;   // 16 bf16 = 32B
            uint32_t ah[16], al[16], bh[8], bl[8];
            #pragma unroll
            for (int mt = 0; mt < 4; mt++)
                ldm_x4(&ah[mt * 4], sAh_b + a_off + kadd + mt * (16 * PITCH * 2));
            #pragma unroll
            for (int nt2 = 0; nt2 < 2; nt2++)
                ldm_x4(&bh[nt2 * 4], sBh_b + b_off + kadd + nt2 * (16 * PITCH * 2));
            #pragma unroll
            for (int mt = 0; mt < 4; mt++)
                #pragma unroll
                for (int nt = 0; nt < 4; nt++)
                    mma16816(acc[mt][nt], &ah[mt * 4], &bh[nt * 2]);

            #pragma unroll
            for (int mt = 0; mt < 4; mt++)
                ldm_x4(&al[mt * 4], sAl_b + a_off + kadd + mt * (16 * PITCH * 2));
            #pragma unroll
            for (int mt = 0; mt < 4; mt++)
                #pragma unroll
                for (int nt = 0; nt < 4; nt++)
                    mma16816(acc[mt][nt], &al[mt * 4], &bh[nt * 2]);

            #pragma unroll
            for (int nt2 = 0; nt2 < 2; nt2++)
                ldm_x4(&bl[nt2 * 4], sBl_b + b_off + kadd + nt2 * (16 * PITCH * 2));
            #pragma unroll
            for (int mt = 0; mt < 4; mt++)
                #pragma unroll
                for (int nt = 0; nt < 4; nt++)
                    mma16816(acc[mt][nt], &ah[mt * 4], &bl[nt * 2]);
        }
        __syncthreads();
    }

    // Epilogue: bias add + scatter to [B, NH, S, HD]; 2 floats per store
    #pragma unroll
    for (int mt = 0; mt < 4; mt++) {
        #pragma unroll
        for (int nt = 0; nt < 4; nt++) {
            const int n  = n0 + wn + nt * 8 + (lane & 3) * 2;
            const int h  = n >> 6;
            const int d  = n & 63;
            const float b0 = __ldg(&bias[n]);
            const float b1 = __ldg(&bias[n + 1]);
            #pragma unroll
            for (int half = 0; half < 2; half++) {
                const int m  = m0 + wm + mt * 16 + (lane >> 2) + half * 8;
                const int b_ = m >> 8;
                const int s  = m & 255;
                float2 v = make_float2(acc[mt][nt][half * 2] + b0,
                                       acc[mt][nt][half * 2 + 1] + b1);
                *(float2*)&dst[(size_t)((b_ * NH + h) * SS + s) * HD + d] = v;
            }
        }
    }
}

// ---------------------------------------------------------------------------
// Kernel 2: scores = softmax( (Q K^T / 8) * (w*CM + bc) + mask ), write probs.
// ---------------------------------------------------------------------------
__global__ __launch_bounds__(256) void scores_kernel(
    const float* __restrict__ CM,     // [B,1,S,S]
    const float* __restrict__ MSK,    // [B,1,1,S]
    const float* __restrict__ wcm_p,
    const float* __restrict__ bcm_p)
{
    extern __shared__ float sm[];
    float* Qs = sm;            // [d*64 + m]
    float* KT = sm + 64 * 64;  // [d*256 + j]

    const int bh = blockIdx.y;
    const int qt = blockIdx.x;          // 0..3
    const int b  = bh / NH;
    const int tid = threadIdx.x;

    const float* Q = g_q + (size_t)bh * SS * HD;
    const float* K = g_k + (size_t)bh * SS * HD;

    for (int idx = tid; idx < 64 * 16; idx += 256) {
        const int row = idx >> 4;
        const int c4  = (idx & 15) * 4;
        float4 v = *(const float4*)&Q[(size_t)(qt * 64 + row) * HD + c4];
        Qs[(c4 + 0) * 64 + row] = v.x;
        Qs[(c4 + 1) * 64 + row] = v.y;
        Qs[(c4 + 2) * 64 + row] = v.z;
        Qs[(c4 + 3) * 64 + row] = v.w;
    }
    for (int idx = tid; idx < 256 * 16; idx += 256) {
        const int j  = idx >> 4;
        const int c4 = (idx & 15) * 4;
        float4 v = *(const float4*)&K[(size_t)j * HD + c4];
        KT[(c4 + 0) * 256 + j] = v.x;
        KT[(c4 + 1) * 256 + j] = v.y;
        KT[(c4 + 2) * 256 + j] = v.z;
        KT[(c4 + 3) * 256 + j] = v.w;
    }
    __syncthreads();

    const int trow = tid >> 5;
    const int lane = tid & 31;

    float acc[8][8];
    #pragma unroll
    for (int i = 0; i < 8; i++)
        #pragma unroll
        for (int t = 0; t < 8; t++) acc[i][t] = 0.f;

    #pragma unroll 4
    for (int d = 0; d < 64; d++) {
        float a[8], bb[8];
        *(float4*)(a)     = *(const float4*)&Qs[d * 64 + trow * 8];
        *(float4*)(a + 4) = *(const float4*)&Qs[d * 64 + trow * 8 + 4];
        #pragma unroll
        for (int t = 0; t < 8; t++) bb[t] = KT[d * 256 + lane + 32 * t];
        #pragma unroll
        for (int i = 0; i < 8; i++)
            #pragma unroll
            for (int t = 0; t < 8; t++)
                acc[i][t] += a[i] * bb[t];
    }

    const float wcm = wcm_p[0];
    const float bcm = bcm_p[0];

    #pragma unroll
    for (int i = 0; i < 8; i++) {
        const int r = qt * 64 + trow * 8 + i;
        float s[8];
        float mx = -1e30f;
        #pragma unroll
        for (int t = 0; t < 8; t++) {
            const int c = lane + 32 * t;
            const float cmv = wcm * CM[(size_t)b * SS * SS + (size_t)r * SS + c] + bcm;
            s[t] = acc[i][t] * 0.125f * cmv + MSK[b * SS + c];
            mx = fmaxf(mx, s[t]);
        }
        #pragma unroll
        for (int o = 16; o; o >>= 1) mx = fmaxf(mx, __shfl_xor_sync(0xffffffffu, mx, o));
        float sum = 0.f;
        #pragma unroll
        for (int t = 0; t < 8; t++) { s[t] = __expf(s[t] - mx); sum += s[t]; }
        #pragma unroll
        for (int o = 16; o; o >>= 1) sum += __shfl_xor_sync(0xffffffffu, sum, o);
        const float inv = 1.f / sum;
        float* prow = g_p + ((size_t)bh * SS + r) * SS;
        #pragma unroll
        for (int t = 0; t < 8; t++) prow[lane + 32 * t] = s[t] * inv;
    }
}

// ---------------------------------------------------------------------------
// Kernel 3: ctx = P @ V
// ---------------------------------------------------------------------------
__global__ __launch_bounds__(256) void pv_kernel(float* __restrict__ out)
{
    __shared__ float PsT[32][128];
    __shared__ float Vs[32][64];

    const int bh = blockIdx.y;
    const int mt = blockIdx.x;
    const int b  = bh / NH;
    const int h  = bh % NH;
    const int m0 = mt * 128;
    const int tid = threadIdx.x;
    const int ty = tid >> 4, tx = tid & 15;

    const float* P = g_p + (size_t)bh * SS * SS;
    const float* V = g_v + (size_t)bh * SS * HD;

    float acc[8][4];
    #pragma unroll
    for (int i = 0; i < 8; i++)
        #pragma unroll
        for (int j = 0; j < 4; j++) acc[i][j] = 0.f;

    for (int k0 = 0; k0 < SS; k0 += 32) {
        #pragma unroll
        for (int u = 0; u < 4; u++) {
            const int idx = tid + u * 256;
            const int row = idx >> 3;
            const int c4  = (idx & 7) * 4;
            float4 v = *(const float4*)&P[(size_t)(m0 + row) * SS + k0 + c4];
            PsT[c4 + 0][row] = v.x;
            PsT[c4 + 1][row] = v.y;
            PsT[c4 + 2][row] = v.z;
            PsT[c4 + 3][row] = v.w;
        }
        #pragma unroll
        for (int u = 0; u < 2; u++) {
            const int idx = tid + u * 256;
            const int row = idx >> 4;
            const int c4  = (idx & 15) * 4;
            *(float4*)&Vs[row][c4] = *(const float4*)&V[(size_t)(k0 + row) * HD + c4];
        }
        __syncthreads();

        #pragma unroll
        for (int k = 0; k < 32; k++) {
            float a[8], bb[4];
            *(float4*)(a)     = *(const float4*)&PsT[k][ty * 8];
            *(float4*)(a + 4) = *(const float4*)&PsT[k][ty * 8 + 4];
            *(float4*)(bb)    = *(const float4*)&Vs[k][tx * 4];
            #pragma unroll
            for (int i = 0; i < 8; i++)
                #pragma unroll
                for (int j = 0; j < 4; j++)
                    acc[i][j] += a[i] * bb[j];
        }
        __syncthreads();
    }

    #pragma unroll
    for (int i = 0; i < 8; i++) {
        const int s = m0 + ty * 8 + i;
        float* orow = out + (size_t)(b * SS + s) * HH + h * HD + tx * 4;
        #pragma unroll
        for (int j = 0; j < 4; j++) orow[j] = acc[i][j];
    }
}

// ---------------------------------------------------------------------------
extern "C" void kernel_launch(void* const* d_in, const int* in_sizes, int n_in,
                              void* d_out, int out_size)
{
    const float* X    = (const float*)d_in[0];
    const float* CM   = (const float*)d_in[1];
    const float* MSK  = (const float*)d_in[2];
    const float* Wq   = (const float*)d_in[3];
    const float* bq   = (const float*)d_in[4];
    const float* Wk   = (const float*)d_in[5];
    const float* bk   = (const float*)d_in[6];
    const float* Wv   = (const float*)d_in[7];
    const float* bv   = (const float*)d_in[8];
    const float* wcm  = (const float*)d_in[9];
    const float* bcm  = (const float*)d_in[10];
    float* out = (float*)d_out;

    // 0) split-precision operand prep
    prep_x<<<(BB * SS * HH / 4 + 255) / 256, 256>>>(X);
    prep_w<<<(3 * HH * HH + 255) / 256, 256>>>(Wq, Wk, Wv);

    // 1) QKV projections on tensor cores (mma.sync bf16, 3-term split)
    qkv_mma<<<dim3(64, 18), 256>>>(bq, bk, bv);

    // 2) scores + softmax (80 KB dynamic smem)
    const size_t smem2 = (64 * 64 + 64 * 256) * sizeof(float);
    cudaFuncSetAttribute(scores_kernel, cudaFuncAttributeMaxDynamicSharedMemorySize, (int)smem2);
    scores_kernel<<<dim3(4, BH), 256, smem2>>>(CM, MSK, wcm, bcm);

    // 3) P @ V
    pv_kernel<<<dim3(2, BH), 256>>>(out);
}

// round 4
// speedup vs baseline: 2.5741x; 1.4096x over previous
#include <cuda_runtime.h>
#include <cuda_bf16.h>
#include <cstdint>

#define BB 32
#define SS 256
#define HH 768
#define NH 12
#define HD 64
#define BH (BB*NH)          // 384

// bf16 hi/lo split operands (device globals; no runtime allocation)
__device__ unsigned short g_xh[(size_t)BB*SS*HH];
__device__ unsigned short g_xl[(size_t)BB*SS*HH];
__device__ unsigned short g_wh[(size_t)3*HH*HH];   // transposed: [nw][n][k]
__device__ unsigned short g_wl[(size_t)3*HH*HH];
// QKV outputs as bf16 hi/lo, layout [bh][s][d]
__device__ unsigned short g_qh[(size_t)BH*SS*HD];
__device__ unsigned short g_ql[(size_t)BH*SS*HD];
__device__ unsigned short g_kh[(size_t)BH*SS*HD];
__device__ unsigned short g_kl[(size_t)BH*SS*HD];
__device__ unsigned short g_vh[(size_t)BH*SS*HD];
__device__ unsigned short g_vl[(size_t)BH*SS*HD];

// ---------------------------------------------------------------------------
// mma.sync helpers (sm_80-era PTX; legal on plain sm_100 target)
// ---------------------------------------------------------------------------
__device__ __forceinline__ uint32_t smem_to_u32(const void* p) {
    uint32_t a;
    asm("{ .reg .u64 t; cvta.to.shared.u64 t, %1; cvt.u32.u64 %0, t; }" : "=r"(a) : "l"(p));
    return a;
}
__device__ __forceinline__ void ldm_x4(uint32_t* r, uint32_t addr) {
    asm volatile("ldmatrix.sync.aligned.m8n8.x4.shared.b16 {%0,%1,%2,%3}, [%4];"
        : "=r"(r[0]), "=r"(r[1]), "=r"(r[2]), "=r"(r[3]) : "r"(addr));
}
__device__ __forceinline__ void ldm_x4_t(uint32_t* r, uint32_t addr) {
    asm volatile("ldmatrix.sync.aligned.m8n8.x4.trans.shared.b16 {%0,%1,%2,%3}, [%4];"
        : "=r"(r[0]), "=r"(r[1]), "=r"(r[2]), "=r"(r[3]) : "r"(addr));
}
__device__ __forceinline__ void mma16816(float* c, const uint32_t* a, const uint32_t* b) {
    asm volatile("mma.sync.aligned.m16n8k16.row.col.f32.bf16.bf16.f32 "
        "{%0,%1,%2,%3}, {%4,%5,%6,%7}, {%8,%9}, {%0,%1,%2,%3};"
        : "+f"(c[0]), "+f"(c[1]), "+f"(c[2]), "+f"(c[3])
        : "r"(a[0]), "r"(a[1]), "r"(a[2]), "r"(a[3]), "r"(b[0]), "r"(b[1]));
}
// split two floats into packed bf16x2 hi + lo
__device__ __forceinline__ void split2(float x0, float x1, uint32_t& h, uint32_t& l) {
    __nv_bfloat16 h0 = __float2bfloat16(x0), h1 = __float2bfloat16(x1);
    __nv_bfloat16 l0 = __float2bfloat16(x0 - __bfloat162float(h0));
    __nv_bfloat16 l1 = __float2bfloat16(x1 - __bfloat162float(h1));
    h = (uint32_t)__bfloat16_as_ushort(h0) | ((uint32_t)__bfloat16_as_ushort(h1) << 16);
    l = (uint32_t)__bfloat16_as_ushort(l0) | ((uint32_t)__bfloat16_as_ushort(l1) << 16);
}

// ---------------------------------------------------------------------------
// Prep kernels: fp32 -> bf16 hi/lo split
// ---------------------------------------------------------------------------
__global__ __launch_bounds__(256) void prep_x(const float* __restrict__ X)
{
    const size_t i4 = (size_t)blockIdx.x * 256 + threadIdx.x;
    if (i4 * 4 >= (size_t)BB * SS * HH) return;
    float4 v = ((const float4*)X)[i4];
    __nv_bfloat16 h0 = __float2bfloat16(v.x), h1 = __float2bfloat16(v.y);
    __nv_bfloat16 h2 = __float2bfloat16(v.z), h3 = __float2bfloat16(v.w);
    __nv_bfloat16 l0 = __float2bfloat16(v.x - __bfloat162float(h0));
    __nv_bfloat16 l1 = __float2bfloat16(v.y - __bfloat162float(h1));
    __nv_bfloat16 l2 = __float2bfloat16(v.z - __bfloat162float(h2));
    __nv_bfloat16 l3 = __float2bfloat16(v.w - __bfloat162float(h3));
    ((ushort4*)g_xh)[i4] = make_ushort4(__bfloat16_as_ushort(h0), __bfloat16_as_ushort(h1),
                                        __bfloat16_as_ushort(h2), __bfloat16_as_ushort(h3));
    ((ushort4*)g_xl)[i4] = make_ushort4(__bfloat16_as_ushort(l0), __bfloat16_as_ushort(l1),
                                        __bfloat16_as_ushort(l2), __bfloat16_as_ushort(l3));
}

__global__ __launch_bounds__(256) void prep_w(
    const float* __restrict__ Wq, const float* __restrict__ Wk, const float* __restrict__ Wv)
{
    const size_t idx = (size_t)blockIdx.x * 256 + threadIdx.x;   // [nw][n][k]
    if (idx >= (size_t)3 * HH * HH) return;
    const int k  = idx % HH;
    const int n  = (idx / HH) % HH;
    const int nw = idx / (HH * HH);
    const float* W = (nw == 0) ? Wq : (nw == 1) ? Wk : Wv;
    float v = __ldg(&W[(size_t)k * HH + n]);
    __nv_bfloat16 h = __float2bfloat16(v);
    __nv_bfloat16 l = __float2bfloat16(v - __bfloat162float(h));
    g_wh[idx] = __bfloat16_as_ushort(h);
    g_wl[idx] = __bfloat16_as_ushort(l);
}

// ---------------------------------------------------------------------------
// QKV GEMM via mma.sync bf16 (3-term split, fp32 accumulators).
// CTA tile 128x128, K chunk 32; 8 warps 2x4; warp tile 64x32.
// Epilogue emits bf16 hi/lo Q/K/V in [bh][s][d] layout.
// ---------------------------------------------------------------------------
#define PITCH 40     // bf16 elements per smem row (80B) -> conflict-free ldmatrix

__global__ __launch_bounds__(256, 2) void qkv_mma(
    const float* __restrict__ bq, const float* __restrict__ bk, const float* __restrict__ bv)
{
    __shared__ __align__(16) unsigned short sAh[128 * PITCH];
    __shared__ __align__(16) unsigned short sAl[128 * PITCH];
    __shared__ __align__(16) unsigned short sBh[128 * PITCH];
    __shared__ __align__(16) unsigned short sBl[128 * PITCH];

    const int tid  = threadIdx.x;
    const int wid  = tid >> 5;
    const int lane = tid & 31;

    const int m0 = blockIdx.x * 128;
    const int nw = blockIdx.y / 6;
    const int n0 = (blockIdx.y % 6) * 128;

    const float* bias = (nw == 0) ? bq : (nw == 1) ? bk : bv;
    unsigned short* dsth = (nw == 0) ? g_qh : (nw == 1) ? g_kh : g_vh;
    unsigned short* dstl = (nw == 0) ? g_ql : (nw == 1) ? g_kl : g_vl;

    const int wm = (wid >> 2) * 64;
    const int wn = (wid & 3) * 32;

    const uint32_t sAh_b = smem_to_u32(sAh);
    const uint32_t sAl_b = smem_to_u32(sAl);
    const uint32_t sBh_b = smem_to_u32(sBh);
    const uint32_t sBl_b = smem_to_u32(sBl);

    const uint32_t a_off = ((wm + (lane & 15)) * PITCH + (lane >> 4) * 8) * 2;
    const uint32_t b_off = ((wn + (lane >> 4) * 8 + (lane & 7)) * PITCH + ((lane >> 3) & 1) * 8) * 2;

    float acc[4][4][4];
    #pragma unroll
    for (int i = 0; i < 4; i++)
        #pragma unroll
        for (int j = 0; j < 4; j++)
            #pragma unroll
            for (int c = 0; c < 4; c++) acc[i][j][c] = 0.f;

    for (int chunk = 0; chunk < 24; chunk++) {
        const int k0 = chunk * 32;
        #pragma unroll
        for (int i = 0; i < 2; i++) {
            const int idx = tid + i * 256;
            const int r  = idx >> 2;
            const int sg = idx & 3;
            const size_t ga = (size_t)(m0 + r) * HH + k0 + sg * 8;
            const size_t gb = ((size_t)nw * HH + n0 + r) * HH + k0 + sg * 8;
            const uint32_t so = r * PITCH + sg * 8;
            *(uint4*)&sAh[so] = *(const uint4*)&g_xh[ga];
            *(uint4*)&sAl[so] = *(const uint4*)&g_xl[ga];
            *(uint4*)&sBh[so] = *(const uint4*)&g_wh[gb];
            *(uint4*)&sBl[so] = *(const uint4*)&g_wl[gb];
        }
        __syncthreads();

        #pragma unroll
        for (int ks = 0; ks < 2; ks++) {
            const uint32_t kadd = ks * 16 * 2;
            uint32_t ah[16], al[16], bh[8], bl[8];
            #pragma unroll
            for (int mt = 0; mt < 4; mt++)
                ldm_x4(&ah[mt * 4], sAh_b + a_off + kadd + mt * (16 * PITCH * 2));
            #pragma unroll
            for (int nt2 = 0; nt2 < 2; nt2++)
                ldm_x4(&bh[nt2 * 4], sBh_b + b_off + kadd + nt2 * (16 * PITCH * 2));
            #pragma unroll
            for (int mt = 0; mt < 4; mt++)
                #pragma unroll
                for (int nt = 0; nt < 4; nt++)
                    mma16816(acc[mt][nt], &ah[mt * 4], &bh[nt * 2]);
            #pragma unroll
            for (int mt = 0; mt < 4; mt++)
                ldm_x4(&al[mt * 4], sAl_b + a_off + kadd + mt * (16 * PITCH * 2));
            #pragma unroll
            for (int mt = 0; mt < 4; mt++)
                #pragma unroll
                for (int nt = 0; nt < 4; nt++)
                    mma16816(acc[mt][nt], &al[mt * 4], &bh[nt * 2]);
            #pragma unroll
            for (int nt2 = 0; nt2 < 2; nt2++)
                ldm_x4(&bl[nt2 * 4], sBl_b + b_off + kadd + nt2 * (16 * PITCH * 2));
            #pragma unroll
            for (int mt = 0; mt < 4; mt++)
                #pragma unroll
                for (int nt = 0; nt < 4; nt++)
                    mma16816(acc[mt][nt], &ah[mt * 4], &bl[nt * 2]);
        }
        __syncthreads();
    }

    // Epilogue: bias + bf16 hi/lo split, scatter to [bh][s][d]
    #pragma unroll
    for (int mt = 0; mt < 4; mt++) {
        #pragma unroll
        for (int nt = 0; nt < 4; nt++) {
            const int n  = n0 + wn + nt * 8 + (lane & 3) * 2;
            const int h  = n >> 6;
            const int d  = n & 63;
            const float b0 = __ldg(&bias[n]);
            const float b1 = __ldg(&bias[n + 1]);
            #pragma unroll
            for (int half = 0; half < 2; half++) {
                const int m  = m0 + wm + mt * 16 + (lane >> 2) + half * 8;
                const int b_ = m >> 8;
                const int s  = m & 255;
                const float x0 = acc[mt][nt][half * 2]     + b0;
                const float x1 = acc[mt][nt][half * 2 + 1] + b1;
                uint32_t hh, ll;
                split2(x0, x1, hh, ll);
                const size_t di = (size_t)((b_ * NH + h) * SS + s) * HD + d;
                *(uint32_t*)&dsth[di] = hh;
                *(uint32_t*)&dstl[di] = ll;
            }
        }
    }
}

// ---------------------------------------------------------------------------
// Fused attention: scores (QK^T, 3-term) -> cm-scale+mask -> softmax -> P@V
// (3-term). One CTA per (b,h,64-row q tile). 8 warps: wm=wid>>1, wn=wid&1.
// Warp tile phase1: 16q x 128k. Phase3: 16q x 64d partial over 128 k.
// ---------------------------------------------------------------------------
#define P2 72                       // smem pitch (elements) for 64-wide tiles
#define OFF_Q_H  0                  // 64*72*2      = 9216
#define OFF_Q_L  9216               // 9216
#define OFF_K_H  18432              // 256*72*2     = 36864
#define OFF_K_L  55296              // 36864
#define OFF_MAX  92160              // 64*2 floats  = 512
#define OFF_SUM  92672              // 512
#define ATT_SMEM 93184
#define OFF_CTX  0                  // reuse Q region: 4*16*66*4 = 16896 < 18432

__global__ __launch_bounds__(256) void att_kernel(
    const float* __restrict__ CM, const float* __restrict__ MSK,
    const float* __restrict__ wcm_p, const float* __restrict__ bcm_p,
    float* __restrict__ out)
{
    extern __shared__ __align__(16) char smem[];
    const uint32_t sb = smem_to_u32(smem);

    const int tid  = threadIdx.x;
    const int wid  = tid >> 5;
    const int lane = tid & 31;
    const int wm = wid >> 1;        // 0..3
    const int wn = wid & 1;         // 0..1

    const int bh = blockIdx.y;
    const int qt = blockIdx.x;      // 0..3
    const int b  = bh / NH;
    const int h  = bh % NH;

    // Stage Q (64 rows) and K (256 rows), hi+lo
    #pragma unroll
    for (int i = 0; i < 2; i++) {
        const int s_ = tid + i * 256;
        const int r = s_ >> 3, sg = s_ & 7;
        const size_t gi = ((size_t)bh * SS + qt * 64 + r) * HD + sg * 8;
        const uint32_t so = (r * P2 + sg * 8) * 2;
        *(uint4*)(smem + OFF_Q_H + so) = *(const uint4*)(g_qh + gi);
        *(uint4*)(smem + OFF_Q_L + so) = *(const uint4*)(g_ql + gi);
    }
    #pragma unroll
    for (int i = 0; i < 8; i++) {
        const int s_ = tid + i * 256;
        const int r = s_ >> 3, sg = s_ & 7;
        const size_t gi = ((size_t)bh * SS + r) * HD + sg * 8;
        const uint32_t so = (r * P2 + sg * 8) * 2;
        *(uint4*)(smem + OFF_K_H + so) = *(const uint4*)(g_kh + gi);
        *(uint4*)(smem + OFF_K_L + so) = *(const uint4*)(g_kl + gi);
    }
    __syncthreads();

    // Phase 1: S = Q K^T (3-term split). acc[nt][4], nt over 16 n8-tiles.
    const uint32_t a_off = ((wm * 16 + (lane & 15)) * P2 + (lane >> 4) * 8) * 2;
    const uint32_t b_off = ((wn * 128 + (lane >> 4) * 8 + (lane & 7)) * P2 + ((lane >> 3) & 1) * 8) * 2;

    float acc[16][4];
    #pragma unroll
    for (int nt = 0; nt < 16; nt++)
        #pragma unroll
        for (int c = 0; c < 4; c++) acc[nt][c] = 0.f;

    #pragma unroll
    for (int ks = 0; ks < 4; ks++) {
        const uint32_t kadd = ks * 32;
        uint32_t ah[4], al[4], bb[32];
        ldm_x4(ah, sb + OFF_Q_H + a_off + kadd);
        ldm_x4(al, sb + OFF_Q_L + a_off + kadd);
        #pragma unroll
        for (int g = 0; g < 8; g++)
            ldm_x4(&bb[g * 4], sb + OFF_K_H + b_off + kadd + g * (16 * P2 * 2));
        #pragma unroll
        for (int nt = 0; nt < 16; nt++) mma16816(acc[nt], ah, &bb[nt * 2]);
        #pragma unroll
        for (int nt = 0; nt < 16; nt++) mma16816(acc[nt], al, &bb[nt * 2]);
        #pragma unroll
        for (int g = 0; g < 8; g++)
            ldm_x4(&bb[g * 4], sb + OFF_K_L + b_off + kadd + g * (16 * P2 * 2));
        #pragma unroll
        for (int nt = 0; nt < 16; nt++) mma16816(acc[nt], ah, &bb[nt * 2]);
    }

    // Phase 2: scale by cm, add mask, softmax over 256 cols (2 warps share rows)
    const int rl0 = wm * 16 + (lane >> 2);
    const int rl1 = rl0 + 8;
    const int r0g = qt * 64 + rl0;
    const int r1g = qt * 64 + rl1;
    const float wv  = __ldg(wcm_p);
    const float bvv = __ldg(bcm_p);
    const float* CMb = CM + (size_t)b * SS * SS;

    float mx0 = -1e30f, mx1 = -1e30f;
    #pragma unroll
    for (int nt = 0; nt < 16; nt++) {
        const int c = wn * 128 + nt * 8 + (lane & 3) * 2;
        float2 cm0 = *(const float2*)&CMb[(size_t)r0g * SS + c];
        float2 cm1 = *(const float2*)&CMb[(size_t)r1g * SS + c];
        float2 mk  = *(const float2*)&MSK[b * SS + c];
        acc[nt][0] = acc[nt][0] * 0.125f * fmaf(wv, cm0.x, bvv) + mk.x;
        acc[nt][1] = acc[nt][1] * 0.125f * fmaf(wv, cm0.y, bvv) + mk.y;
        acc[nt][2] = acc[nt][2] * 0.125f * fmaf(wv, cm1.x, bvv) + mk.x;
        acc[nt][3] = acc[nt][3] * 0.125f * fmaf(wv, cm1.y, bvv) + mk.y;
        mx0 = fmaxf(mx0, fmaxf(acc[nt][0], acc[nt][1]));
        mx1 = fmaxf(mx1, fmaxf(acc[nt][2], acc[nt][3]));
    }
    mx0 = fmaxf(mx0, __shfl_xor_sync(~0u, mx0, 1));
    mx0 = fmaxf(mx0, __shfl_xor_sync(~0u, mx0, 2));
    mx1 = fmaxf(mx1, __shfl_xor_sync(~0u, mx1, 1));
    mx1 = fmaxf(mx1, __shfl_xor_sync(~0u, mx1, 2));
    float* smax = (float*)(smem + OFF_MAX);
    float* ssum = (float*)(smem + OFF_SUM);
    if ((lane & 3) == 0) { smax[rl0 * 2 + wn] = mx0; smax[rl1 * 2 + wn] = mx1; }
    __syncthreads();   // [A] — phase 1 done in all warps; K smem reusable

    // Stage V into the K buffers (overlaps with softmax below)
    #pragma unroll
    for (int i = 0; i < 8; i++) {
        const int s_ = tid + i * 256;
        const int r = s_ >> 3, sg = s_ & 7;
        const size_t gi = ((size_t)bh * SS + r) * HD + sg * 8;
        const uint32_t so = (r * P2 + sg * 8) * 2;
        *(uint4*)(smem + OFF_K_H + so) = *(const uint4*)(g_vh + gi);
        *(uint4*)(smem + OFF_K_L + so) = *(const uint4*)(g_vl + gi);
    }

    const float m0 = fmaxf(smax[rl0 * 2], smax[rl0 * 2 + 1]);
    const float m1 = fmaxf(smax[rl1 * 2], smax[rl1 * 2 + 1]);
    float sum0 = 0.f, sum1 = 0.f;
    #pragma unroll
    for (int nt = 0; nt < 16; nt++) {
        acc[nt][0] = __expf(acc[nt][0] - m0);
        acc[nt][1] = __expf(acc[nt][1] - m0);
        acc[nt][2] = __expf(acc[nt][2] - m1);
        acc[nt][3] = __expf(acc[nt][3] - m1);
        sum0 += acc[nt][0] + acc[nt][1];
        sum1 += acc[nt][2] + acc[nt][3];
    }
    sum0 += __shfl_xor_sync(~0u, sum0, 1);
    sum0 += __shfl_xor_sync(~0u, sum0, 2);
    sum1 += __shfl_xor_sync(~0u, sum1, 1);
    sum1 += __shfl_xor_sync(~0u, sum1, 2);
    if ((lane & 3) == 0) { ssum[rl0 * 2 + wn] = sum0; ssum[rl1 * 2 + wn] = sum1; }
    __syncthreads();   // [B] — sums visible; V staging complete

    const float inv0 = 1.f / (ssum[rl0 * 2] + ssum[rl0 * 2 + 1]);
    const float inv1 = 1.f / (ssum[rl1 * 2] + ssum[rl1 * 2 + 1]);

    // Normalize + split P into bf16 A-fragments (C->A register reuse)
    uint32_t aPh[8][4], aPl[8][4];
    #pragma unroll
    for (int ks = 0; ks < 8; ks++) {
        const int lo = 2 * ks, hi = 2 * ks + 1;
        split2(acc[lo][0] * inv0, acc[lo][1] * inv0, aPh[ks][0], aPl[ks][0]);
        split2(acc[lo][2] * inv1, acc[lo][3] * inv1, aPh[ks][1], aPl[ks][1]);
        split2(acc[hi][0] * inv0, acc[hi][1] * inv0, aPh[ks][2], aPl[ks][2]);
        split2(acc[hi][2] * inv1, acc[hi][3] * inv1, aPh[ks][3], aPl[ks][3]);
    }

    // Phase 3: partial ctx = P(k-range of this warp) @ V
    float ctx[8][4];
    #pragma unroll
    for (int d8 = 0; d8 < 8; d8++)
        #pragma unroll
        for (int c = 0; c < 4; c++) ctx[d8][c] = 0.f;

    const uint32_t vj = lane >> 3, vi = lane & 7;
    #pragma unroll
    for (int ks = 0; ks < 8; ks++) {
        const uint32_t vrow = wn * 128 + ks * 16 + (vj & 1) * 8 + vi;
        const uint32_t vcol = (vj >> 1) * 8;
        uint32_t vb[16];
        #pragma unroll
        for (int g = 0; g < 4; g++)
            ldm_x4_t(&vb[g * 4], sb + OFF_K_H + (vrow * P2 + g * 16 + vcol) * 2);
        #pragma unroll
        for (int d8 = 0; d8 < 8; d8++) mma16816(ctx[d8], aPh[ks], &vb[d8 * 2]);
        #pragma unroll
        for (int d8 = 0; d8 < 8; d8++) mma16816(ctx[d8], aPl[ks], &vb[d8 * 2]);
        #pragma unroll
        for (int g = 0; g < 4; g++)
            ldm_x4_t(&vb[g * 4], sb + OFF_K_L + (vrow * P2 + g * 16 + vcol) * 2);
        #pragma unroll
        for (int d8 = 0; d8 < 8; d8++) mma16816(ctx[d8], aPh[ks], &vb[d8 * 2]);
    }

    // Cross-warp (wn) reduction of ctx partials, then write out [B,S,H]
    float* sctx = (float*)(smem + OFF_CTX);   // [wm*16+row][66]
    if (wn == 1) {
        #pragma unroll
        for (int d8 = 0; d8 < 8; d8++) {
            const int d = d8 * 8 + (lane & 3) * 2;
            *(float2*)&sctx[(wm * 16 + (lane >> 2)) * 66 + d]     = make_float2(ctx[d8][0], ctx[d8][1]);
            *(float2*)&sctx[(wm * 16 + (lane >> 2) + 8) * 66 + d] = make_float2(ctx[d8][2], ctx[d8][3]);
        }
    }
    __syncthreads();   // [C]
    if (wn == 0) {
        #pragma unroll
        for (int d8 = 0; d8 < 8; d8++) {
            const int d = d8 * 8 + (lane & 3) * 2;
            float2 p0 = *(const float2*)&sctx[(wm * 16 + (lane >> 2)) * 66 + d];
            float2 p1 = *(const float2*)&sctx[(wm * 16 + (lane >> 2) + 8) * 66 + d];
            p0.x += ctx[d8][0]; p0.y += ctx[d8][1];
            p1.x += ctx[d8][2]; p1.y += ctx[d8][3];
            const int s0 = qt * 64 + wm * 16 + (lane >> 2);
            *(float2*)&out[(size_t)(b * SS + s0) * HH + h * HD + d]       = p0;
            *(float2*)&out[(size_t)(b * SS + s0 + 8) * HH + h * HD + d]   = p1;
        }
    }
}

// ---------------------------------------------------------------------------
extern "C" void kernel_launch(void* const* d_in, const int* in_sizes, int n_in,
                              void* d_out, int out_size)
{
    const float* X    = (const float*)d_in[0];
    const float* CM   = (const float*)d_in[1];
    const float* MSK  = (const float*)d_in[2];
    const float* Wq   = (const float*)d_in[3];
    const float* bq   = (const float*)d_in[4];
    const float* Wk   = (const float*)d_in[5];
    const float* bk   = (const float*)d_in[6];
    const float* Wv   = (const float*)d_in[7];
    const float* bv   = (const float*)d_in[8];
    const float* wcm  = (const float*)d_in[9];
    const float* bcm  = (const float*)d_in[10];
    float* out = (float*)d_out;

    prep_x<<<(BB * SS * HH / 4 + 255) / 256, 256>>>(X);
    prep_w<<<(3 * HH * HH + 255) / 256, 256>>>(Wq, Wk, Wv);

    qkv_mma<<<dim3(64, 18), 256>>>(bq, bk, bv);

    cudaFuncSetAttribute(att_kernel, cudaFuncAttributeMaxDynamicSharedMemorySize, ATT_SMEM);
    att_kernel<<<dim3(4, BH), 256, ATT_SMEM>>>(CM, MSK, wcm, bcm, out);
}

// round 5
// speedup vs baseline: 2.7820x; 1.0808x over previous
#include <cuda_runtime.h>
#include <cuda_bf16.h>
#include <cstdint>

#define BB 32
#define SS 256
#define HH 768
#define NH 12
#define HD 64
#define BH (BB*NH)          // 384

// bf16 hi/lo split operands (device globals; no runtime allocation)
__device__ unsigned short g_xh[(size_t)BB*SS*HH];
__device__ unsigned short g_xl[(size_t)BB*SS*HH];
__device__ unsigned short g_wh[(size_t)3*HH*HH];   // transposed: [nw][n][k]
__device__ unsigned short g_wl[(size_t)3*HH*HH];
// QKV outputs as bf16 hi/lo, layout [bh][s][d]
__device__ unsigned short g_qh[(size_t)BH*SS*HD];
__device__ unsigned short g_ql[(size_t)BH*SS*HD];
__device__ unsigned short g_kh[(size_t)BH*SS*HD];
__device__ unsigned short g_kl[(size_t)BH*SS*HD];
__device__ unsigned short g_vh[(size_t)BH*SS*HD];
__device__ unsigned short g_vl[(size_t)BH*SS*HD];

// ---------------------------------------------------------------------------
// PTX helpers (sm_80-era; legal on plain sm_100 target)
// ---------------------------------------------------------------------------
__device__ __forceinline__ uint32_t smem_to_u32(const void* p) {
    uint32_t a;
    asm("{ .reg .u64 t; cvta.to.shared.u64 t, %1; cvt.u32.u64 %0, t; }" : "=r"(a) : "l"(p));
    return a;
}
__device__ __forceinline__ void cp16(uint32_t dst, const void* src) {
    asm volatile("cp.async.cg.shared.global [%0], [%1], 16;" :: "r"(dst), "l"(src));
}
#define CP_COMMIT() asm volatile("cp.async.commit_group;" ::: "memory")
#define CP_WAIT(n)  asm volatile("cp.async.wait_group %0;" :: "n"(n) : "memory")
__device__ __forceinline__ void ldm_x4(uint32_t* r, uint32_t addr) {
    asm volatile("ldmatrix.sync.aligned.m8n8.x4.shared.b16 {%0,%1,%2,%3}, [%4];"
        : "=r"(r[0]), "=r"(r[1]), "=r"(r[2]), "=r"(r[3]) : "r"(addr));
}
__device__ __forceinline__ void ldm_x4_t(uint32_t* r, uint32_t addr) {
    asm volatile("ldmatrix.sync.aligned.m8n8.x4.trans.shared.b16 {%0,%1,%2,%3}, [%4];"
        : "=r"(r[0]), "=r"(r[1]), "=r"(r[2]), "=r"(r[3]) : "r"(addr));
}
__device__ __forceinline__ void mma16816(float* c, const uint32_t* a, const uint32_t* b) {
    asm volatile("mma.sync.aligned.m16n8k16.row.col.f32.bf16.bf16.f32 "
        "{%0,%1,%2,%3}, {%4,%5,%6,%7}, {%8,%9}, {%0,%1,%2,%3};"
        : "+f"(c[0]), "+f"(c[1]), "+f"(c[2]), "+f"(c[3])
        : "r"(a[0]), "r"(a[1]), "r"(a[2]), "r"(a[3]), "r"(b[0]), "r"(b[1]));
}
__device__ __forceinline__ void split2(float x0, float x1, uint32_t& h, uint32_t& l) {
    __nv_bfloat16 h0 = __float2bfloat16(x0), h1 = __float2bfloat16(x1);
    __nv_bfloat16 l0 = __float2bfloat16(x0 - __bfloat162float(h0));
    __nv_bfloat16 l1 = __float2bfloat16(x1 - __bfloat162float(h1));
    h = (uint32_t)__bfloat16_as_ushort(h0) | ((uint32_t)__bfloat16_as_ushort(h1) << 16);
    l = (uint32_t)__bfloat16_as_ushort(l0) | ((uint32_t)__bfloat16_as_ushort(l1) << 16);
}

// ---------------------------------------------------------------------------
// Prep kernels: fp32 -> bf16 hi/lo split
// ---------------------------------------------------------------------------
__global__ __launch_bounds__(256) void prep_x(const float* __restrict__ X)
{
    const size_t i4 = (size_t)blockIdx.x * 256 + threadIdx.x;
    if (i4 * 4 >= (size_t)BB * SS * HH) return;
    float4 v = ((const float4*)X)[i4];
    __nv_bfloat16 h0 = __float2bfloat16(v.x), h1 = __float2bfloat16(v.y);
    __nv_bfloat16 h2 = __float2bfloat16(v.z), h3 = __float2bfloat16(v.w);
    __nv_bfloat16 l0 = __float2bfloat16(v.x - __bfloat162float(h0));
    __nv_bfloat16 l1 = __float2bfloat16(v.y - __bfloat162float(h1));
    __nv_bfloat16 l2 = __float2bfloat16(v.z - __bfloat162float(h2));
    __nv_bfloat16 l3 = __float2bfloat16(v.w - __bfloat162float(h3));
    ((ushort4*)g_xh)[i4] = make_ushort4(__bfloat16_as_ushort(h0), __bfloat16_as_ushort(h1),
                                        __bfloat16_as_ushort(h2), __bfloat16_as_ushort(h3));
    ((ushort4*)g_xl)[i4] = make_ushort4(__bfloat16_as_ushort(l0), __bfloat16_as_ushort(l1),
                                        __bfloat16_as_ushort(l2), __bfloat16_as_ushort(l3));
}

__global__ __launch_bounds__(256) void prep_w(
    const float* __restrict__ Wq, const float* __restrict__ Wk, const float* __restrict__ Wv)
{
    const size_t idx = (size_t)blockIdx.x * 256 + threadIdx.x;   // [nw][n][k]
    if (idx >= (size_t)3 * HH * HH) return;
    const int k  = idx % HH;
    const int n  = (idx / HH) % HH;
    const int nw = idx / (HH * HH);
    const float* W = (nw == 0) ? Wq : (nw == 1) ? Wk : Wv;
    float v = __ldg(&W[(size_t)k * HH + n]);
    __nv_bfloat16 h = __float2bfloat16(v);
    __nv_bfloat16 l = __float2bfloat16(v - __bfloat162float(h));
    g_wh[idx] = __bfloat16_as_ushort(h);
    g_wl[idx] = __bfloat16_as_ushort(l);
}

// ---------------------------------------------------------------------------
// QKV GEMM via mma.sync bf16 (3-term split), cp.async double-buffered.
// CTA tile 128x128, K chunk 32; 8 warps 2x4; warp tile 64x32.
// ---------------------------------------------------------------------------
#define PITCH 40                        // bf16/row (80B) -> conflict-free ldmatrix
#define QST_A_H 0
#define QST_A_L 10240
#define QST_B_H 20480
#define QST_B_L 30720
#define QST_STRIDE 40960                // bytes per stage
#define QKV_SMEM (2 * QST_STRIDE)       // 81920

__global__ __launch_bounds__(256, 2) void qkv_mma(
    const float* __restrict__ bq, const float* __restrict__ bk, const float* __restrict__ bv)
{
    extern __shared__ __align__(16) char qsm[];
    const uint32_t sb = smem_to_u32(qsm);

    const int tid  = threadIdx.x;
    const int wid  = tid >> 5;
    const int lane = tid & 31;

    const int m0 = blockIdx.x * 128;
    const int nw = blockIdx.y / 6;
    const int n0 = (blockIdx.y % 6) * 128;

    const float* bias = (nw == 0) ? bq : (nw == 1) ? bk : bv;
    unsigned short* dsth = (nw == 0) ? g_qh : (nw == 1) ? g_kh : g_vh;
    unsigned short* dstl = (nw == 0) ? g_ql : (nw == 1) ? g_kl : g_vl;

    const int wm = (wid >> 2) * 64;
    const int wn = (wid & 3) * 32;

    // per-thread staging indices: idx 0..511 over 2 iters
    const int r_st  = tid >> 1;              // row 0..127 (iter adds via idx)
    // (recomputed in the lambda-less loop below)

    const uint32_t a_off = ((wm + (lane & 15)) * PITCH + (lane >> 4) * 8) * 2;
    const uint32_t b_off = ((wn + (lane >> 4) * 8 + (lane & 7)) * PITCH + ((lane >> 3) & 1) * 8) * 2;

    float acc[4][4][4];
    #pragma unroll
    for (int i = 0; i < 4; i++)
        #pragma unroll
        for (int j = 0; j < 4; j++)
            #pragma unroll
            for (int c = 0; c < 4; c++) acc[i][j][c] = 0.f;

    // ---- issue staging for chunk c into stage s ----
    #define QKV_STAGE(c_, s_)                                                        \
    do {                                                                             \
        const int k0_ = (c_) * 32;                                                   \
        const uint32_t stb_ = sb + (s_) * QST_STRIDE;                                \
        _Pragma("unroll")                                                            \
        for (int i_ = 0; i_ < 2; i_++) {                                             \
            const int idx_ = tid + i_ * 256;                                         \
            const int r_  = idx_ >> 2;                                               \
            const int sg_ = idx_ & 3;                                                \
            const size_t ga_ = (size_t)(m0 + r_) * HH + k0_ + sg_ * 8;               \
            const size_t gb_ = ((size_t)nw * HH + n0 + r_) * HH + k0_ + sg_ * 8;     \
            const uint32_t so_ = (r_ * PITCH + sg_ * 8) * 2;                         \
            cp16(stb_ + QST_A_H + so_, g_xh + ga_);                                  \
            cp16(stb_ + QST_A_L + so_, g_xl + ga_);                                  \
            cp16(stb_ + QST_B_H + so_, g_wh + gb_);                                  \
            cp16(stb_ + QST_B_L + so_, g_wl + gb_);                                  \
        }                                                                            \
        CP_COMMIT();                                                                 \
    } while (0)

    QKV_STAGE(0, 0);

    for (int chunk = 0; chunk < 24; chunk++) {
        const int st = chunk & 1;
        if (chunk + 1 < 24) {
            QKV_STAGE(chunk + 1, st ^ 1);
            CP_WAIT(1);
        } else {
            CP_WAIT(0);
        }
        __syncthreads();

        const uint32_t sAh_b = sb + st * QST_STRIDE + QST_A_H;
        const uint32_t sAl_b = sb + st * QST_STRIDE + QST_A_L;
        const uint32_t sBh_b = sb + st * QST_STRIDE + QST_B_H;
        const uint32_t sBl_b = sb + st * QST_STRIDE + QST_B_L;

        #pragma unroll
        for (int ks = 0; ks < 2; ks++) {
            const uint32_t kadd = ks * 16 * 2;
            uint32_t ah[16], al[16], bh[8], bl[8];
            #pragma unroll
            for (int mt = 0; mt < 4; mt++)
                ldm_x4(&ah[mt * 4], sAh_b + a_off + kadd + mt * (16 * PITCH * 2));
            #pragma unroll
            for (int nt2 = 0; nt2 < 2; nt2++)
                ldm_x4(&bh[nt2 * 4], sBh_b + b_off + kadd + nt2 * (16 * PITCH * 2));
            #pragma unroll
            for (int mt = 0; mt < 4; mt++)
                #pragma unroll
                for (int nt = 0; nt < 4; nt++)
                    mma16816(acc[mt][nt], &ah[mt * 4], &bh[nt * 2]);
            #pragma unroll
            for (int mt = 0; mt < 4; mt++)
                ldm_x4(&al[mt * 4], sAl_b + a_off + kadd + mt * (16 * PITCH * 2));
            #pragma unroll
            for (int mt = 0; mt < 4; mt++)
                #pragma unroll
                for (int nt = 0; nt < 4; nt++)
                    mma16816(acc[mt][nt], &al[mt * 4], &bh[nt * 2]);
            #pragma unroll
            for (int nt2 = 0; nt2 < 2; nt2++)
                ldm_x4(&bl[nt2 * 4], sBl_b + b_off + kadd + nt2 * (16 * PITCH * 2));
            #pragma unroll
            for (int mt = 0; mt < 4; mt++)
                #pragma unroll
                for (int nt = 0; nt < 4; nt++)
                    mma16816(acc[mt][nt], &ah[mt * 4], &bl[nt * 2]);
        }
        __syncthreads();
    }

    // Epilogue: bias + bf16 hi/lo split, scatter to [bh][s][d]
    #pragma unroll
    for (int mt = 0; mt < 4; mt++) {
        #pragma unroll
        for (int nt = 0; nt < 4; nt++) {
            const int n  = n0 + wn + nt * 8 + (lane & 3) * 2;
            const int h  = n >> 6;
            const int d  = n & 63;
            const float b0 = __ldg(&bias[n]);
            const float b1 = __ldg(&bias[n + 1]);
            #pragma unroll
            for (int half = 0; half < 2; half++) {
                const int m  = m0 + wm + mt * 16 + (lane >> 2) + half * 8;
                const int b_ = m >> 8;
                const int s  = m & 255;
                const float x0 = acc[mt][nt][half * 2]     + b0;
                const float x1 = acc[mt][nt][half * 2 + 1] + b1;
                uint32_t hh, ll;
                split2(x0, x1, hh, ll);
                const size_t di = (size_t)((b_ * NH + h) * SS + s) * HD + d;
                *(uint32_t*)&dsth[di] = hh;
                *(uint32_t*)&dstl[di] = ll;
            }
        }
    }
}

// ---------------------------------------------------------------------------
// Fused attention: scores (QK^T, 3-term) -> cm-scale+mask -> softmax -> P@V
// ---------------------------------------------------------------------------
#define P2 72
#define OFF_Q_H  0
#define OFF_Q_L  9216
#define OFF_K_H  18432
#define OFF_K_L  55296
#define OFF_MAX  92160
#define OFF_SUM  92672
#define ATT_SMEM 93184
#define OFF_CTX  0

__global__ __launch_bounds__(256, 2) void att_kernel(
    const float* __restrict__ CM, const float* __restrict__ MSK,
    const float* __restrict__ wcm_p, const float* __restrict__ bcm_p,
    float* __restrict__ out)
{
    extern __shared__ __align__(16) char smem[];
    const uint32_t sb = smem_to_u32(smem);

    const int tid  = threadIdx.x;
    const int wid  = tid >> 5;
    const int lane = tid & 31;
    const int wm = wid >> 1;
    const int wn = wid & 1;

    const int bh = blockIdx.y;
    const int qt = blockIdx.x;
    const int b  = bh / NH;
    const int h  = bh % NH;

    // Stage Q (64 rows) and K (256 rows), hi+lo (cp.async)
    #pragma unroll
    for (int i = 0; i < 2; i++) {
        const int s_ = tid + i * 256;
        const int r = s_ >> 3, sg = s_ & 7;
        const size_t gi = ((size_t)bh * SS + qt * 64 + r) * HD + sg * 8;
        const uint32_t so = (r * P2 + sg * 8) * 2;
        cp16(sb + OFF_Q_H + so, g_qh + gi);
        cp16(sb + OFF_Q_L + so, g_ql + gi);
    }
    #pragma unroll
    for (int i = 0; i < 8; i++) {
        const int s_ = tid + i * 256;
        const int r = s_ >> 3, sg = s_ & 7;
        const size_t gi = ((size_t)bh * SS + r) * HD + sg * 8;
        const uint32_t so = (r * P2 + sg * 8) * 2;
        cp16(sb + OFF_K_H + so, g_kh + gi);
        cp16(sb + OFF_K_L + so, g_kl + gi);
    }
    CP_COMMIT();
    CP_WAIT(0);
    __syncthreads();

    // Phase 1: S = Q K^T (3-term split)
    const uint32_t a_off = ((wm * 16 + (lane & 15)) * P2 + (lane >> 4) * 8) * 2;
    const uint32_t b_off = ((wn * 128 + (lane >> 4) * 8 + (lane & 7)) * P2 + ((lane >> 3) & 1) * 8) * 2;

    float acc[16][4];
    #pragma unroll
    for (int nt = 0; nt < 16; nt++)
        #pragma unroll
        for (int c = 0; c < 4; c++) acc[nt][c] = 0.f;

    #pragma unroll
    for (int ks = 0; ks < 4; ks++) {
        const uint32_t kadd = ks * 32;
        uint32_t ah[4], al[4], bb[32];
        ldm_x4(ah, sb + OFF_Q_H + a_off + kadd);
        ldm_x4(al, sb + OFF_Q_L + a_off + kadd);
        #pragma unroll
        for (int g = 0; g < 8; g++)
            ldm_x4(&bb[g * 4], sb + OFF_K_H + b_off + kadd + g * (16 * P2 * 2));
        #pragma unroll
        for (int nt = 0; nt < 16; nt++) mma16816(acc[nt], ah, &bb[nt * 2]);
        #pragma unroll
        for (int nt = 0; nt < 16; nt++) mma16816(acc[nt], al, &bb[nt * 2]);
        #pragma unroll
        for (int g = 0; g < 8; g++)
            ldm_x4(&bb[g * 4], sb + OFF_K_L + b_off + kadd + g * (16 * P2 * 2));
        #pragma unroll
        for (int nt = 0; nt < 16; nt++) mma16816(acc[nt], ah, &bb[nt * 2]);
    }

    // Phase 2: scale by cm, add mask, softmax over 256 cols
    const int rl0 = wm * 16 + (lane >> 2);
    const int rl1 = rl0 + 8;
    const int r0g = qt * 64 + rl0;
    const int r1g = qt * 64 + rl1;
    const float wv  = __ldg(wcm_p);
    const float bvv = __ldg(bcm_p);
    const float* CMb = CM + (size_t)b * SS * SS;

    float mx0 = -1e30f, mx1 = -1e30f;
    #pragma unroll
    for (int nt = 0; nt < 16; nt++) {
        const int c = wn * 128 + nt * 8 + (lane & 3) * 2;
        float2 cm0 = *(const float2*)&CMb[(size_t)r0g * SS + c];
        float2 cm1 = *(const float2*)&CMb[(size_t)r1g * SS + c];
        float2 mk  = *(const float2*)&MSK[b * SS + c];
        acc[nt][0] = acc[nt][0] * 0.125f * fmaf(wv, cm0.x, bvv) + mk.x;
        acc[nt][1] = acc[nt][1] * 0.125f * fmaf(wv, cm0.y, bvv) + mk.y;
        acc[nt][2] = acc[nt][2] * 0.125f * fmaf(wv, cm1.x, bvv) + mk.x;
        acc[nt][3] = acc[nt][3] * 0.125f * fmaf(wv, cm1.y, bvv) + mk.y;
        mx0 = fmaxf(mx0, fmaxf(acc[nt][0], acc[nt][1]));
        mx1 = fmaxf(mx1, fmaxf(acc[nt][2], acc[nt][3]));
    }
    mx0 = fmaxf(mx0, __shfl_xor_sync(~0u, mx0, 1));
    mx0 = fmaxf(mx0, __shfl_xor_sync(~0u, mx0, 2));
    mx1 = fmaxf(mx1, __shfl_xor_sync(~0u, mx1, 1));
    mx1 = fmaxf(mx1, __shfl_xor_sync(~0u, mx1, 2));
    float* smax = (float*)(smem + OFF_MAX);
    float* ssum = (float*)(smem + OFF_SUM);
    if ((lane & 3) == 0) { smax[rl0 * 2 + wn] = mx0; smax[rl1 * 2 + wn] = mx1; }
    __syncthreads();   // [A] — phase 1 done in all warps; K smem reusable

    // Stage V into K buffers via cp.async (overlaps the softmax math below)
    #pragma unroll
    for (int i = 0; i < 8; i++) {
        const int s_ = tid + i * 256;
        const int r = s_ >> 3, sg = s_ & 7;
        const size_t gi = ((size_t)bh * SS + r) * HD + sg * 8;
        const uint32_t so = (r * P2 + sg * 8) * 2;
        cp16(sb + OFF_K_H + so, g_vh + gi);
        cp16(sb + OFF_K_L + so, g_vl + gi);
    }
    CP_COMMIT();

    const float m0 = fmaxf(smax[rl0 * 2], smax[rl0 * 2 + 1]);
    const float m1 = fmaxf(smax[rl1 * 2], smax[rl1 * 2 + 1]);
    float sum0 = 0.f, sum1 = 0.f;
    #pragma unroll
    for (int nt = 0; nt < 16; nt++) {
        acc[nt][0] = __expf(acc[nt][0] - m0);
        acc[nt][1] = __expf(acc[nt][1] - m0);
        acc[nt][2] = __expf(acc[nt][2] - m1);
        acc[nt][3] = __expf(acc[nt][3] - m1);
        sum0 += acc[nt][0] + acc[nt][1];
        sum1 += acc[nt][2] + acc[nt][3];
    }
    sum0 += __shfl_xor_sync(~0u, sum0, 1);
    sum0 += __shfl_xor_sync(~0u, sum0, 2);
    sum1 += __shfl_xor_sync(~0u, sum1, 1);
    sum1 += __shfl_xor_sync(~0u, sum1, 2);
    if ((lane & 3) == 0) { ssum[rl0 * 2 + wn] = sum0; ssum[rl1 * 2 + wn] = sum1; }
    CP_WAIT(0);
    __syncthreads();   // [B] — sums visible; V staging complete

    const float inv0 = 1.f / (ssum[rl0 * 2] + ssum[rl0 * 2 + 1]);
    const float inv1 = 1.f / (ssum[rl1 * 2] + ssum[rl1 * 2 + 1]);

    // Normalize + split P into bf16 A-fragments
    uint32_t aPh[8][4], aPl[8][4];
    #pragma unroll
    for (int ks = 0; ks < 8; ks++) {
        const int lo = 2 * ks, hi = 2 * ks + 1;
        split2(acc[lo][0] * inv0, acc[lo][1] * inv0, aPh[ks][0], aPl[ks][0]);
        split2(acc[lo][2] * inv1, acc[lo][3] * inv1, aPh[ks][1], aPl[ks][1]);
        split2(acc[hi][0] * inv0, acc[hi][1] * inv0, aPh[ks][2], aPl[ks][2]);
        split2(acc[hi][2] * inv1, acc[hi][3] * inv1, aPh[ks][3], aPl[ks][3]);
    }

    // Phase 3: partial ctx = P(k-range of this warp) @ V
    float ctx[8][4];
    #pragma unroll
    for (int d8 = 0; d8 < 8; d8++)
        #pragma unroll
        for (int c = 0; c < 4; c++) ctx[d8][c] = 0.f;

    const uint32_t vj = lane >> 3, vi = lane & 7;
    #pragma unroll
    for (int ks = 0; ks < 8; ks++) {
        const uint32_t vrow = wn * 128 + ks * 16 + (vj & 1) * 8 + vi;
        const uint32_t vcol = (vj >> 1) * 8;
        uint32_t vb[16];
        #pragma unroll
        for (int g = 0; g < 4; g++)
            ldm_x4_t(&vb[g * 4], sb + OFF_K_H + (vrow * P2 + g * 16 + vcol) * 2);
        #pragma unroll
        for (int d8 = 0; d8 < 8; d8++) mma16816(ctx[d8], aPh[ks], &vb[d8 * 2]);
        #pragma unroll
        for (int d8 = 0; d8 < 8; d8++) mma16816(ctx[d8], aPl[ks], &vb[d8 * 2]);
        #pragma unroll
        for (int g = 0; g < 4; g++)
            ldm_x4_t(&vb[g * 4], sb + OFF_K_L + (vrow * P2 + g * 16 + vcol) * 2);
        #pragma unroll
        for (int d8 = 0; d8 < 8; d8++) mma16816(ctx[d8], aPh[ks], &vb[d8 * 2]);
    }

    // Cross-warp (wn) reduction of ctx partials, then write out [B,S,H]
    float* sctx = (float*)(smem + OFF_CTX);
    if (wn == 1) {
        #pragma unroll
        for (int d8 = 0; d8 < 8; d8++) {
            const int d = d8 * 8 + (lane & 3) * 2;
            *(float2*)&sctx[(wm * 16 + (lane >> 2)) * 66 + d]     = make_float2(ctx[d8][0], ctx[d8][1]);
            *(float2*)&sctx[(wm * 16 + (lane >> 2) + 8) * 66 + d] = make_float2(ctx[d8][2], ctx[d8][3]);
        }
    }
    __syncthreads();   // [C]
    if (wn == 0) {
        #pragma unroll
        for (int d8 = 0; d8 < 8; d8++) {
            const int d = d8 * 8 + (lane & 3) * 2;
            float2 p0 = *(const float2*)&sctx[(wm * 16 + (lane >> 2)) * 66 + d];
            float2 p1 = *(const float2*)&sctx[(wm * 16 + (lane >> 2) + 8) * 66 + d];
            p0.x += ctx[d8][0]; p0.y += ctx[d8][1];
            p1.x += ctx[d8][2]; p1.y += ctx[d8][3];
            const int s0 = qt * 64 + wm * 16 + (lane >> 2);
            *(float2*)&out[(size_t)(b * SS + s0) * HH + h * HD + d]       = p0;
            *(float2*)&out[(size_t)(b * SS + s0 + 8) * HH + h * HD + d]   = p1;
        }
    }
}

// ---------------------------------------------------------------------------
extern "C" void kernel_launch(void* const* d_in, const int* in_sizes, int n_in,
                              void* d_out, int out_size)
{
    const float* X    = (const float*)d_in[0];
    const float* CM   = (const float*)d_in[1];
    const float* MSK  = (const float*)d_in[2];
    const float* Wq   = (const float*)d_in[3];
    const float* bq   = (const float*)d_in[4];
    const float* Wk   = (const float*)d_in[5];
    const float* bk   = (const float*)d_in[6];
    const float* Wv   = (const float*)d_in[7];
    const float* bv   = (const float*)d_in[8];
    const float* wcm  = (const float*)d_in[9];
    const float* bcm  = (const float*)d_in[10];
    float* out = (float*)d_out;

    prep_x<<<(BB * SS * HH / 4 + 255) / 256, 256>>>(X);
    prep_w<<<(3 * HH * HH + 255) / 256, 256>>>(Wq, Wk, Wv);

    cudaFuncSetAttribute(qkv_mma, cudaFuncAttributeMaxDynamicSharedMemorySize, QKV_SMEM);
    qkv_mma<<<dim3(64, 18), 256, QKV_SMEM>>>(bq, bk, bv);

    cudaFuncSetAttribute(att_kernel, cudaFuncAttributeMaxDynamicSharedMemorySize, ATT_SMEM);
    att_kernel<<<dim3(4, BH), 256, ATT_SMEM>>>(CM, MSK, wcm, bcm, out);
}

// round 6
// speedup vs baseline: 3.3135x; 1.1910x over previous
#include <cuda_runtime.h>
#include <cuda_bf16.h>
#include <cstdint>

#define BB 32
#define SS 256
#define HH 768
#define NH 12
#define HD 64
#define BH (BB*NH)          // 384

// Scratch (device globals; no runtime allocation)
__device__ float g_x [(size_t)BB*SS*HH];           // X, rna-rounded to tf32
__device__ float g_wt[(size_t)3*HH*HH];            // W transposed [nw][n][k], tf32
// QKV outputs as bf16 hi/lo, layout [bh][s][d]
__device__ unsigned short g_qh[(size_t)BH*SS*HD];
__device__ unsigned short g_ql[(size_t)BH*SS*HD];
__device__ unsigned short g_kh[(size_t)BH*SS*HD];
__device__ unsigned short g_kl[(size_t)BH*SS*HD];
__device__ unsigned short g_vh[(size_t)BH*SS*HD];
__device__ unsigned short g_vl[(size_t)BH*SS*HD];

// ---------------------------------------------------------------------------
// PTX helpers (sm_80-era; legal on plain sm_100 target)
// ---------------------------------------------------------------------------
__device__ __forceinline__ uint32_t smem_to_u32(const void* p) {
    uint32_t a;
    asm("{ .reg .u64 t; cvta.to.shared.u64 t, %1; cvt.u32.u64 %0, t; }" : "=r"(a) : "l"(p));
    return a;
}
__device__ __forceinline__ void cp16(uint32_t dst, const void* src) {
    asm volatile("cp.async.cg.shared.global [%0], [%1], 16;" :: "r"(dst), "l"(src));
}
#define CP_COMMIT() asm volatile("cp.async.commit_group;" ::: "memory")
#define CP_WAIT(n)  asm volatile("cp.async.wait_group %0;" :: "n"(n) : "memory")
__device__ __forceinline__ void ldm_x4(uint32_t* r, uint32_t addr) {
    asm volatile("ldmatrix.sync.aligned.m8n8.x4.shared.b16 {%0,%1,%2,%3}, [%4];"
        : "=r"(r[0]), "=r"(r[1]), "=r"(r[2]), "=r"(r[3]) : "r"(addr));
}
__device__ __forceinline__ void ldm_x4_t(uint32_t* r, uint32_t addr) {
    asm volatile("ldmatrix.sync.aligned.m8n8.x4.trans.shared.b16 {%0,%1,%2,%3}, [%4];"
        : "=r"(r[0]), "=r"(r[1]), "=r"(r[2]), "=r"(r[3]) : "r"(addr));
}
__device__ __forceinline__ void mma16816(float* c, const uint32_t* a, const uint32_t* b) {
    asm volatile("mma.sync.aligned.m16n8k16.row.col.f32.bf16.bf16.f32 "
        "{%0,%1,%2,%3}, {%4,%5,%6,%7}, {%8,%9}, {%0,%1,%2,%3};"
        : "+f"(c[0]), "+f"(c[1]), "+f"(c[2]), "+f"(c[3])
        : "r"(a[0]), "r"(a[1]), "r"(a[2]), "r"(a[3]), "r"(b[0]), "r"(b[1]));
}
__device__ __forceinline__ void mma_tf32(float* c, const uint32_t* a, uint32_t b0, uint32_t b1) {
    asm volatile("mma.sync.aligned.m16n8k8.row.col.f32.tf32.tf32.f32 "
        "{%0,%1,%2,%3}, {%4,%5,%6,%7}, {%8,%9}, {%0,%1,%2,%3};"
        : "+f"(c[0]), "+f"(c[1]), "+f"(c[2]), "+f"(c[3])
        : "r"(a[0]), "r"(a[1]), "r"(a[2]), "r"(a[3]), "r"(b0), "r"(b1));
}
__device__ __forceinline__ float to_tf32(float x) {
    uint32_t u = __float_as_uint(x), o;
    asm("cvt.rna.tf32.f32 %0, %1;" : "=r"(o) : "r"(u));
    return __uint_as_float(o);
}
__device__ __forceinline__ void split2(float x0, float x1, uint32_t& h, uint32_t& l) {
    __nv_bfloat16 h0 = __float2bfloat16(x0), h1 = __float2bfloat16(x1);
    __nv_bfloat16 l0 = __float2bfloat16(x0 - __bfloat162float(h0));
    __nv_bfloat16 l1 = __float2bfloat16(x1 - __bfloat162float(h1));
    h = (uint32_t)__bfloat16_as_ushort(h0) | ((uint32_t)__bfloat16_as_ushort(h1) << 16);
    l = (uint32_t)__bfloat16_as_ushort(l0) | ((uint32_t)__bfloat16_as_ushort(l1) << 16);
}

// ---------------------------------------------------------------------------
// Prep: X -> tf32 (rna), W -> transposed tf32 (coalesced tile transpose)
// ---------------------------------------------------------------------------
__global__ __launch_bounds__(256) void prep_x(const float* __restrict__ X)
{
    const size_t i4 = (size_t)blockIdx.x * 256 + threadIdx.x;
    if (i4 * 4 >= (size_t)BB * SS * HH) return;
    float4 v = ((const float4*)X)[i4];
    v.x = to_tf32(v.x); v.y = to_tf32(v.y); v.z = to_tf32(v.z); v.w = to_tf32(v.w);
    ((float4*)g_x)[i4] = v;
}

__global__ __launch_bounds__(256) void prep_w(
    const float* __restrict__ Wq, const float* __restrict__ Wk, const float* __restrict__ Wv)
{
    __shared__ float tile[32][33];
    const int nw = blockIdx.z;
    const float* W = (nw == 0) ? Wq : (nw == 1) ? Wk : Wv;
    const int k0 = blockIdx.x * 32;
    const int n0 = blockIdx.y * 32;
    const int tx = threadIdx.x & 31;
    const int ty = threadIdx.x >> 5;          // 0..7
    #pragma unroll
    for (int s = 0; s < 32; s += 8)
        tile[ty + s][tx] = W[(size_t)(k0 + ty + s) * HH + n0 + tx];
    __syncthreads();
    #pragma unroll
    for (int s = 0; s < 32; s += 8)
        g_wt[((size_t)nw * HH + n0 + ty + s) * HH + k0 + tx] = to_tf32(tile[tx][ty + s]);
}

// ---------------------------------------------------------------------------
// QKV GEMM via mma.sync tf32 (single term), cp.async double-buffered.
// CTA tile 128x128, K chunk 32; 8 warps 2x4; warp tile 64x32.
// ---------------------------------------------------------------------------
#define PITCH_F 36                      // floats per smem row (144 B)
#define QST_B  18432                    // B tile offset within stage
#define QST_STRIDE 36864                // bytes per stage
#define QKV_SMEM (2 * QST_STRIDE)       // 73728

__global__ __launch_bounds__(256, 2) void qkv_mma(
    const float* __restrict__ bq, const float* __restrict__ bk, const float* __restrict__ bv)
{
    extern __shared__ __align__(16) char qsm[];
    const uint32_t sb = smem_to_u32(qsm);

    const int tid  = threadIdx.x;
    const int wid  = tid >> 5;
    const int lane = tid & 31;

    const int m0 = blockIdx.x * 128;
    const int nw = blockIdx.y / 6;
    const int n0 = (blockIdx.y % 6) * 128;

    const float* bias = (nw == 0) ? bq : (nw == 1) ? bk : bv;
    unsigned short* dsth = (nw == 0) ? g_qh : (nw == 1) ? g_kh : g_vh;
    unsigned short* dstl = (nw == 0) ? g_ql : (nw == 1) ? g_kl : g_vl;

    const int wm = (wid >> 2) * 64;
    const int wn = (wid & 3) * 32;

    // ldmatrix lane addressing (tf32-as-b16 overlay): row + 16B column select
    const int ar = (lane & 7) + ((lane >> 3) & 1) * 8;
    const uint32_t asel = (lane >> 4) * 16;
    const uint32_t a_off = (uint32_t)(wm + ar) * (PITCH_F * 4) + asel;
    const uint32_t b_off = (uint32_t)(wn + ar) * (PITCH_F * 4) + asel;

    float acc[4][4][4];
    #pragma unroll
    for (int i = 0; i < 4; i++)
        #pragma unroll
        for (int j = 0; j < 4; j++)
            #pragma unroll
            for (int c = 0; c < 4; c++) acc[i][j][c] = 0.f;

    #define QKV_STAGE(c_, s_)                                                        \
    do {                                                                             \
        const int k0_ = (c_) * 32;                                                   \
        const uint32_t stb_ = sb + (s_) * QST_STRIDE;                                \
        _Pragma("unroll")                                                            \
        for (int i_ = 0; i_ < 4; i_++) {                                             \
            const int idx_ = tid + i_ * 256;      /* 0..1023 */                      \
            const int r_  = idx_ >> 3;                                               \
            const int sg_ = idx_ & 7;                                                \
            const size_t ga_ = (size_t)(m0 + r_) * HH + k0_ + sg_ * 4;               \
            const size_t gb_ = ((size_t)nw * HH + n0 + r_) * HH + k0_ + sg_ * 4;     \
            const uint32_t so_ = (r_ * PITCH_F + sg_ * 4) * 4;                       \
            cp16(stb_ + so_, g_x + ga_);                                             \
            cp16(stb_ + QST_B + so_, g_wt + gb_);                                    \
        }                                                                            \
        CP_COMMIT();                                                                 \
    } while (0)

    QKV_STAGE(0, 0);

    for (int chunk = 0; chunk < 24; chunk++) {
        const int st = chunk & 1;
        if (chunk + 1 < 24) {
            QKV_STAGE(chunk + 1, st ^ 1);
            CP_WAIT(1);
        } else {
            CP_WAIT(0);
        }
        __syncthreads();

        const uint32_t sA = sb + st * QST_STRIDE;
        const uint32_t sB = sA + QST_B;

        #pragma unroll
        for (int j = 0; j < 4; j++) {              // k8 steps within chunk
            const uint32_t kadd = j * 32;          // 8 floats = 32 B
            uint32_t a[16], bb[8];
            #pragma unroll
            for (int mt = 0; mt < 4; mt++)
                ldm_x4(&a[mt * 4], sA + a_off + kadd + mt * (16 * PITCH_F * 4));
            #pragma unroll
            for (int p = 0; p < 2; p++)
                ldm_x4(&bb[p * 4], sB + b_off + kadd + p * (16 * PITCH_F * 4));
            // fragment mapping: for pair p, n8-tile 2p   -> {bb[4p+0], bb[4p+2]}
            //                            n8-tile 2p+1 -> {bb[4p+1], bb[4p+3]}
            #pragma unroll
            for (int mt = 0; mt < 4; mt++) {
                mma_tf32(acc[mt][0], &a[mt * 4], bb[0], bb[2]);
                mma_tf32(acc[mt][1], &a[mt * 4], bb[1], bb[3]);
                mma_tf32(acc[mt][2], &a[mt * 4], bb[4], bb[6]);
                mma_tf32(acc[mt][3], &a[mt * 4], bb[5], bb[7]);
            }
        }
        __syncthreads();
    }

    // Epilogue: bias + bf16 hi/lo split, scatter to [bh][s][d]
    #pragma unroll
    for (int mt = 0; mt < 4; mt++) {
        #pragma unroll
        for (int nt = 0; nt < 4; nt++) {
            const int n  = n0 + wn + nt * 8 + (lane & 3) * 2;
            const int h  = n >> 6;
            const int d  = n & 63;
            const float b0 = __ldg(&bias[n]);
            const float b1 = __ldg(&bias[n + 1]);
            #pragma unroll
            for (int half = 0; half < 2; half++) {
                const int m  = m0 + wm + mt * 16 + (lane >> 2) + half * 8;
                const int b_ = m >> 8;
                const int s  = m & 255;
                const float x0 = acc[mt][nt][half * 2]     + b0;
                const float x1 = acc[mt][nt][half * 2 + 1] + b1;
                uint32_t hh, ll;
                split2(x0, x1, hh, ll);
                const size_t di = (size_t)((b_ * NH + h) * SS + s) * HD + d;
                *(uint32_t*)&dsth[di] = hh;
                *(uint32_t*)&dstl[di] = ll;
            }
        }
    }
}

// ---------------------------------------------------------------------------
// Fused attention: scores (QK^T, 3-term bf16) -> cm*scale+mask -> softmax -> P@V
// ---------------------------------------------------------------------------
#define P2 72
#define OFF_Q_H  0
#define OFF_Q_L  9216
#define OFF_K_H  18432
#define OFF_K_L  55296
#define OFF_MAX  92160
#define OFF_SUM  92672
#define ATT_SMEM 93184
#define OFF_CTX  0

__global__ __launch_bounds__(256, 2) void att_kernel(
    const float* __restrict__ CM, const float* __restrict__ MSK,
    const float* __restrict__ wcm_p, const float* __restrict__ bcm_p,
    float* __restrict__ out)
{
    extern __shared__ __align__(16) char smem[];
    const uint32_t sb = smem_to_u32(smem);

    const int tid  = threadIdx.x;
    const int wid  = tid >> 5;
    const int lane = tid & 31;
    const int wm = wid >> 1;
    const int wn = wid & 1;

    const int bh = blockIdx.y;
    const int qt = blockIdx.x;
    const int b  = bh / NH;
    const int h  = bh % NH;

    #pragma unroll
    for (int i = 0; i < 2; i++) {
        const int s_ = tid + i * 256;
        const int r = s_ >> 3, sg = s_ & 7;
        const size_t gi = ((size_t)bh * SS + qt * 64 + r) * HD + sg * 8;
        const uint32_t so = (r * P2 + sg * 8) * 2;
        cp16(sb + OFF_Q_H + so, g_qh + gi);
        cp16(sb + OFF_Q_L + so, g_ql + gi);
    }
    #pragma unroll
    for (int i = 0; i < 8; i++) {
        const int s_ = tid + i * 256;
        const int r = s_ >> 3, sg = s_ & 7;
        const size_t gi = ((size_t)bh * SS + r) * HD + sg * 8;
        const uint32_t so = (r * P2 + sg * 8) * 2;
        cp16(sb + OFF_K_H + so, g_kh + gi);
        cp16(sb + OFF_K_L + so, g_kl + gi);
    }
    CP_COMMIT();
    CP_WAIT(0);
    __syncthreads();

    const uint32_t a_off = ((wm * 16 + (lane & 15)) * P2 + (lane >> 4) * 8) * 2;
    const uint32_t b_off = ((wn * 128 + (lane >> 4) * 8 + (lane & 7)) * P2 + ((lane >> 3) & 1) * 8) * 2;

    float acc[16][4];
    #pragma unroll
    for (int nt = 0; nt < 16; nt++)
        #pragma unroll
        for (int c = 0; c < 4; c++) acc[nt][c] = 0.f;

    #pragma unroll
    for (int ks = 0; ks < 4; ks++) {
        const uint32_t kadd = ks * 32;
        uint32_t ah[4], al[4], bb[32];
        ldm_x4(ah, sb + OFF_Q_H + a_off + kadd);
        ldm_x4(al, sb + OFF_Q_L + a_off + kadd);
        #pragma unroll
        for (int g = 0; g < 8; g++)
            ldm_x4(&bb[g * 4], sb + OFF_K_H + b_off + kadd + g * (16 * P2 * 2));
        #pragma unroll
        for (int nt = 0; nt < 16; nt++) mma16816(acc[nt], ah, &bb[nt * 2]);
        #pragma unroll
        for (int nt = 0; nt < 16; nt++) mma16816(acc[nt], al, &bb[nt * 2]);
        #pragma unroll
        for (int g = 0; g < 8; g++)
            ldm_x4(&bb[g * 4], sb + OFF_K_L + b_off + kadd + g * (16 * P2 * 2));
        #pragma unroll
        for (int nt = 0; nt < 16; nt++) mma16816(acc[nt], ah, &bb[nt * 2]);
    }

    const int rl0 = wm * 16 + (lane >> 2);
    const int rl1 = rl0 + 8;
    const int r0g = qt * 64 + rl0;
    const int r1g = qt * 64 + rl1;
    const float wv  = __ldg(wcm_p);
    const float bvv = __ldg(bcm_p);
    const float* CMb = CM + (size_t)b * SS * SS;

    float mx0 = -1e30f, mx1 = -1e30f;
    #pragma unroll
    for (int nt = 0; nt < 16; nt++) {
        const int c = wn * 128 + nt * 8 + (lane & 3) * 2;
        float2 cm0 = *(const float2*)&CMb[(size_t)r0g * SS + c];
        float2 cm1 = *(const float2*)&CMb[(size_t)r1g * SS + c];
        float2 mk  = *(const float2*)&MSK[b * SS + c];
        acc[nt][0] = acc[nt][0] * 0.125f * fmaf(wv, cm0.x, bvv) + mk.x;
        acc[nt][1] = acc[nt][1] * 0.125f * fmaf(wv, cm0.y, bvv) + mk.y;
        acc[nt][2] = acc[nt][2] * 0.125f * fmaf(wv, cm1.x, bvv) + mk.x;
        acc[nt][3] = acc[nt][3] * 0.125f * fmaf(wv, cm1.y, bvv) + mk.y;
        mx0 = fmaxf(mx0, fmaxf(acc[nt][0], acc[nt][1]));
        mx1 = fmaxf(mx1, fmaxf(acc[nt][2], acc[nt][3]));
    }
    mx0 = fmaxf(mx0, __shfl_xor_sync(~0u, mx0, 1));
    mx0 = fmaxf(mx0, __shfl_xor_sync(~0u, mx0, 2));
    mx1 = fmaxf(mx1, __shfl_xor_sync(~0u, mx1, 1));
    mx1 = fmaxf(mx1, __shfl_xor_sync(~0u, mx1, 2));
    float* smax = (float*)(smem + OFF_MAX);
    float* ssum = (float*)(smem + OFF_SUM);
    if ((lane & 3) == 0) { smax[rl0 * 2 + wn] = mx0; smax[rl1 * 2 + wn] = mx1; }
    __syncthreads();   // [A]

    #pragma unroll
    for (int i = 0; i < 8; i++) {
        const int s_ = tid + i * 256;
        const int r = s_ >> 3, sg = s_ & 7;
        const size_t gi = ((size_t)bh * SS + r) * HD + sg * 8;
        const uint32_t so = (r * P2 + sg * 8) * 2;
        cp16(sb + OFF_K_H + so, g_vh + gi);
        cp16(sb + OFF_K_L + so, g_vl + gi);
    }
    CP_COMMIT();

    const float m0 = fmaxf(smax[rl0 * 2], smax[rl0 * 2 + 1]);
    const float m1 = fmaxf(smax[rl1 * 2], smax[rl1 * 2 + 1]);
    float sum0 = 0.f, sum1 = 0.f;
    #pragma unroll
    for (int nt = 0; nt < 16; nt++) {
        acc[nt][0] = __expf(acc[nt][0] - m0);
        acc[nt][1] = __expf(acc[nt][1] - m0);
        acc[nt][2] = __expf(acc[nt][2] - m1);
        acc[nt][3] = __expf(acc[nt][3] - m1);
        sum0 += acc[nt][0] + acc[nt][1];
        sum1 += acc[nt][2] + acc[nt][3];
    }
    sum0 += __shfl_xor_sync(~0u, sum0, 1);
    sum0 += __shfl_xor_sync(~0u, sum0, 2);
    sum1 += __shfl_xor_sync(~0u, sum1, 1);
    sum1 += __shfl_xor_sync(~0u, sum1, 2);
    if ((lane & 3) == 0) { ssum[rl0 * 2 + wn] = sum0; ssum[rl1 * 2 + wn] = sum1; }
    CP_WAIT(0);
    __syncthreads();   // [B]

    const float inv0 = 1.f / (ssum[rl0 * 2] + ssum[rl0 * 2 + 1]);
    const float inv1 = 1.f / (ssum[rl1 * 2] + ssum[rl1 * 2 + 1]);

    uint32_t aPh[8][4], aPl[8][4];
    #pragma unroll
    for (int ks = 0; ks < 8; ks++) {
        const int lo = 2 * ks, hi = 2 * ks + 1;
        split2(acc[lo][0] * inv0, acc[lo][1] * inv0, aPh[ks][0], aPl[ks][0]);
        split2(acc[lo][2] * inv1, acc[lo][3] * inv1, aPh[ks][1], aPl[ks][1]);
        split2(acc[hi][0] * inv0, acc[hi][1] * inv0, aPh[ks][2], aPl[ks][2]);
        split2(acc[hi][2] * inv1, acc[hi][3] * inv1, aPh[ks][3], aPl[ks][3]);
    }

    float ctx[8][4];
    #pragma unroll
    for (int d8 = 0; d8 < 8; d8++)
        #pragma unroll
        for (int c = 0; c < 4; c++) ctx[d8][c] = 0.f;

    const uint32_t vj = lane >> 3, vi = lane & 7;
    #pragma unroll
    for (int ks = 0; ks < 8; ks++) {
        const uint32_t vrow = wn * 128 + ks * 16 + (vj & 1) * 8 + vi;
        const uint32_t vcol = (vj >> 1) * 8;
        uint32_t vb[16];
        #pragma unroll
        for (int g = 0; g < 4; g++)
            ldm_x4_t(&vb[g * 4], sb + OFF_K_H + (vrow * P2 + g * 16 + vcol) * 2);
        #pragma unroll
        for (int d8 = 0; d8 < 8; d8++) mma16816(ctx[d8], aPh[ks], &vb[d8 * 2]);
        #pragma unroll
        for (int d8 = 0; d8 < 8; d8++) mma16816(ctx[d8], aPl[ks], &vb[d8 * 2]);
        #pragma unroll
        for (int g = 0; g < 4; g++)
            ldm_x4_t(&vb[g * 4], sb + OFF_K_L + (vrow * P2 + g * 16 + vcol) * 2);
        #pragma unroll
        for (int d8 = 0; d8 < 8; d8++) mma16816(ctx[d8], aPh[ks], &vb[d8 * 2]);
    }

    float* sctx = (float*)(smem + OFF_CTX);
    if (wn == 1) {
        #pragma unroll
        for (int d8 = 0; d8 < 8; d8++) {
            const int d = d8 * 8 + (lane & 3) * 2;
            *(float2*)&sctx[(wm * 16 + (lane >> 2)) * 66 + d]     = make_float2(ctx[d8][0], ctx[d8][1]);
            *(float2*)&sctx[(wm * 16 + (lane >> 2) + 8) * 66 + d] = make_float2(ctx[d8][2], ctx[d8][3]);
        }
    }
    __syncthreads();   // [C]
    if (wn == 0) {
        #pragma unroll
        for (int d8 = 0; d8 < 8; d8++) {
            const int d = d8 * 8 + (lane & 3) * 2;
            float2 p0 = *(const float2*)&sctx[(wm * 16 + (lane >> 2)) * 66 + d];
            float2 p1 = *(const float2*)&sctx[(wm * 16 + (lane >> 2) + 8) * 66 + d];
            p0.x += ctx[d8][0]; p0.y += ctx[d8][1];
            p1.x += ctx[d8][2]; p1.y += ctx[d8][3];
            const int s0 = qt * 64 + wm * 16 + (lane >> 2);
            *(float2*)&out[(size_t)(b * SS + s0) * HH + h * HD + d]       = p0;
            *(float2*)&out[(size_t)(b * SS + s0 + 8) * HH + h * HD + d]   = p1;
        }
    }
}

// ---------------------------------------------------------------------------
extern "C" void kernel_launch(void* const* d_in, const int* in_sizes, int n_in,
                              void* d_out, int out_size)
{
    const float* X    = (const float*)d_in[0];
    const float* CM   = (const float*)d_in[1];
    const float* MSK  = (const float*)d_in[2];
    const float* Wq   = (const float*)d_in[3];
    const float* bq   = (const float*)d_in[4];
    const float* Wk   = (const float*)d_in[5];
    const float* bk   = (const float*)d_in[6];
    const float* Wv   = (const float*)d_in[7];
    const float* bv   = (const float*)d_in[8];
    const float* wcm  = (const float*)d_in[9];
    const float* bcm  = (const float*)d_in[10];
    float* out = (float*)d_out;

    prep_x<<<(BB * SS * HH / 4 + 255) / 256, 256>>>(X);
    prep_w<<<dim3(HH / 32, HH / 32, 3), 256>>>(Wq, Wk, Wv);

    cudaFuncSetAttribute(qkv_mma, cudaFuncAttributeMaxDynamicSharedMemorySize, QKV_SMEM);
    qkv_mma<<<dim3(64, 18), 256, QKV_SMEM>>>(bq, bk, bv);

    cudaFuncSetAttribute(att_kernel, cudaFuncAttributeMaxDynamicSharedMemorySize, ATT_SMEM);
    att_kernel<<<dim3(4, BH), 256, ATT_SMEM>>>(CM, MSK, wcm, bcm, out);
}